// round 1
// baseline (speedup 1.0000x reference)
#include <cuda_runtime.h>
#include <cuda_bf16.h>
#include <math.h>

// ---------------------------------------------------------------------------
// HATBlock: window attention + SE channel gate + MLP, fp32 SIMT implementation
// B=4, C=256, H=W=192, WS=8, NH=8, HD=32
// ---------------------------------------------------------------------------

#define BATCH 4
#define DIM   256
#define HH    192
#define WW_   192
#define WS    8
#define NWH   24            // 192/8
#define NWIN  (BATCH*NWH*NWH)   // 2304
#define NTOK  (NWIN*64)         // 147456
#define NH    8
#define HD    32
#define TOK_PER_B (HH*WW_)      // 36864

// -------------------- scratch (device globals; no runtime alloc) -----------
__device__ float g_wins[(size_t)NTOK*256];   // wins / y / xf (151 MB)
__device__ float g_h   [(size_t)NTOK*256];   // LN out / attn out / final (151 MB)
__device__ float g_big [(size_t)NTOK*1024];  // qkv (768 wide) / mlp hidden (604 MB)
__device__ float g_part[576*256];
__device__ float g_gate[BATCH*256];

__device__ __forceinline__ float gelu_exact(float x) {
    return 0.5f * x * (1.0f + erff(x * 0.70710678118654752f));
}

// -------------------- window partition: x[B,C,H,W] -> wins[t,c] ------------
__global__ void k_winpart(const float* __restrict__ x, float* __restrict__ wins) {
    // grid (6,192,32), block (32,8).  blockIdx.z = b*8 + cchunk
    int w0 = blockIdx.x * 32, hh = blockIdx.y;
    int b = blockIdx.z >> 3, c0 = (blockIdx.z & 7) * 32;
    __shared__ float tile[32][33];   // [c][w]
    for (int cc = threadIdx.y; cc < 32; cc += 8)
        tile[cc][threadIdx.x] =
            x[(((size_t)b*256 + c0 + cc)*HH + hh)*WW_ + w0 + threadIdx.x];
    __syncthreads();
    int hw = hh >> 3, i = hh & 7;
    for (int wi = threadIdx.y; wi < 32; wi += 8) {
        int w = w0 + wi, ww = w >> 3, j = w & 7;
        size_t t = (((size_t)b*NWH + hw)*NWH + ww)*64 + i*8 + j;
        wins[t*256 + c0 + threadIdx.x] = tile[threadIdx.x][wi];
    }
}

// -------------------- window reverse: z[t,c] -> out[B,C,H,W] ---------------
__global__ void k_winrev(const float* __restrict__ z, float* __restrict__ out) {
    int w0 = blockIdx.x * 32, hh = blockIdx.y;
    int b = blockIdx.z >> 3, c0 = (blockIdx.z & 7) * 32;
    __shared__ float tile[32][33];   // [w][c]
    int hw = hh >> 3, i = hh & 7;
    for (int wi = threadIdx.y; wi < 32; wi += 8) {
        int w = w0 + wi, ww = w >> 3, j = w & 7;
        size_t t = (((size_t)b*NWH + hw)*NWH + ww)*64 + i*8 + j;
        tile[wi][threadIdx.x] = z[t*256 + c0 + threadIdx.x];
    }
    __syncthreads();
    for (int cc = threadIdx.y; cc < 32; cc += 8)
        out[(((size_t)b*256 + c0 + cc)*HH + hh)*WW_ + w0 + threadIdx.x] =
            tile[threadIdx.x][cc];
}

// -------------------- row LayerNorm (one warp per 256-wide row) ------------
__global__ void __launch_bounds__(256) k_ln(const float* __restrict__ in,
                                            const float* __restrict__ g,
                                            const float* __restrict__ be,
                                            float* __restrict__ out) {
    int row = blockIdx.x * 8 + threadIdx.y;
    const float* p = in + (size_t)row * 256;
    float v[8], s = 0.f, s2 = 0.f;
#pragma unroll
    for (int k = 0; k < 8; k++) {
        v[k] = p[threadIdx.x + 32*k];
        s += v[k]; s2 += v[k]*v[k];
    }
#pragma unroll
    for (int o = 16; o; o >>= 1) {
        s  += __shfl_xor_sync(0xffffffffu, s,  o);
        s2 += __shfl_xor_sync(0xffffffffu, s2, o);
    }
    float mean = s * (1.f/256.f);
    float var  = s2 * (1.f/256.f) - mean*mean;
    float inv  = rsqrtf(var + 1e-5f);
    float* q = out + (size_t)row * 256;
#pragma unroll
    for (int k = 0; k < 8; k++) {
        int c = threadIdx.x + 32*k;
        q[c] = (v[k]-mean)*inv*g[c] + be[c];
    }
}

// -------------------- gate*y (in place) + LayerNorm -------------------------
__global__ void __launch_bounds__(256) k_gate_ln(float* __restrict__ y,
                                                 const float* __restrict__ gate,
                                                 const float* __restrict__ g,
                                                 const float* __restrict__ be,
                                                 float* __restrict__ hm) {
    int row = blockIdx.x * 8 + threadIdx.y;
    int b = row / TOK_PER_B;
    float* p = y + (size_t)row * 256;
    const float* gp = gate + b*256;
    float v[8], s = 0.f, s2 = 0.f;
#pragma unroll
    for (int k = 0; k < 8; k++) {
        int c = threadIdx.x + 32*k;
        float t = p[c] * gp[c];
        p[c] = t;                  // xf written back in place
        v[k] = t; s += t; s2 += t*t;
    }
#pragma unroll
    for (int o = 16; o; o >>= 1) {
        s  += __shfl_xor_sync(0xffffffffu, s,  o);
        s2 += __shfl_xor_sync(0xffffffffu, s2, o);
    }
    float mean = s * (1.f/256.f);
    float var  = s2 * (1.f/256.f) - mean*mean;
    float inv  = rsqrtf(var + 1e-5f);
    float* q = hm + (size_t)row * 256;
#pragma unroll
    for (int k = 0; k < 8; k++) {
        int c = threadIdx.x + 32*k;
        q[c] = (v[k]-mean)*inv*g[c] + be[c];
    }
}

// -------------------- SGEMM: C = act(A @ W + bias [+ R]) -------------------
// A [M,K] rm, W [K,N] rm, C/R [M,N] rm. 128x64x16 tile, 256 thr, 8x4 micro.
__global__ void __launch_bounds__(256) k_sgemm(const float* __restrict__ A,
                                               const float* __restrict__ W,
                                               const float* __restrict__ bias,
                                               const float* __restrict__ R,
                                               float* __restrict__ C,
                                               int N, int K, int act) {
    __shared__ __align__(16) float As[2][16][128];
    __shared__ __align__(16) float Bs[2][16][64];
    const int m0 = blockIdx.x * 128, n0 = blockIdx.y * 64;
    const int tid = threadIdx.x;
    const int tm = tid >> 4, tn = tid & 15;
    const int ar = tid >> 1;
    const int aq = (tid & 1) * 2;         // first float4 k-chunk (0 or 2)
    const int bk = tid >> 4, bn = (tid & 15) * 4;

    const float* Abase = A + (size_t)(m0 + ar) * K + aq * 4;
    const float* Wbase = W + (size_t)bk * N + n0 + bn;

    float acc[8][4] = {};
    float4 va0, va1, vb;

    va0 = *(const float4*)(Abase);
    va1 = *(const float4*)(Abase + 4);
    vb  = *(const float4*)(Wbase);
    const int KT = K / 16;

    As[0][aq*4+0][ar]=va0.x; As[0][aq*4+1][ar]=va0.y;
    As[0][aq*4+2][ar]=va0.z; As[0][aq*4+3][ar]=va0.w;
    As[0][aq*4+4][ar]=va1.x; As[0][aq*4+5][ar]=va1.y;
    As[0][aq*4+6][ar]=va1.z; As[0][aq*4+7][ar]=va1.w;
    *(float4*)&Bs[0][bk][bn] = vb;
    __syncthreads();

    for (int kt = 0; kt < KT; kt++) {
        int cur = kt & 1;
        if (kt + 1 < KT) {
            va0 = *(const float4*)(Abase + (kt+1)*16);
            va1 = *(const float4*)(Abase + (kt+1)*16 + 4);
            vb  = *(const float4*)(Wbase + (size_t)(kt+1)*16*N);
        }
#pragma unroll
        for (int kk = 0; kk < 16; kk++) {
            float4 a0 = *(const float4*)&As[cur][kk][tm*8];
            float4 a1 = *(const float4*)&As[cur][kk][tm*8+4];
            float4 b4 = *(const float4*)&Bs[cur][kk][tn*4];
            float am[8] = {a0.x,a0.y,a0.z,a0.w,a1.x,a1.y,a1.z,a1.w};
            float bv[4] = {b4.x,b4.y,b4.z,b4.w};
#pragma unroll
            for (int i = 0; i < 8; i++)
#pragma unroll
                for (int j = 0; j < 4; j++)
                    acc[i][j] = fmaf(am[i], bv[j], acc[i][j]);
        }
        if (kt + 1 < KT) {
            int nxt = cur ^ 1;
            As[nxt][aq*4+0][ar]=va0.x; As[nxt][aq*4+1][ar]=va0.y;
            As[nxt][aq*4+2][ar]=va0.z; As[nxt][aq*4+3][ar]=va0.w;
            As[nxt][aq*4+4][ar]=va1.x; As[nxt][aq*4+5][ar]=va1.y;
            As[nxt][aq*4+6][ar]=va1.z; As[nxt][aq*4+7][ar]=va1.w;
            *(float4*)&Bs[nxt][bk][bn] = vb;
            __syncthreads();
        }
    }

    float b4[4];
#pragma unroll
    for (int j = 0; j < 4; j++) b4[j] = bias[n0 + tn*4 + j];
#pragma unroll
    for (int i = 0; i < 8; i++) {
        size_t m = (size_t)m0 + tm*8 + i;
        float* cp = C + m*N + n0 + tn*4;
        float vals[4];
#pragma unroll
        for (int j = 0; j < 4; j++) {
            float v = acc[i][j] + b4[j];
            if (R) v += R[m*N + n0 + tn*4 + j];
            if (act) v = gelu_exact(v);
            vals[j] = v;
        }
        *(float4*)cp = make_float4(vals[0], vals[1], vals[2], vals[3]);
    }
}

// -------------------- window attention: one CTA per (window, head) ---------
__global__ void __launch_bounds__(64) k_attn(const float* __restrict__ qkv,
                                             const float* __restrict__ rel_bias,
                                             float* __restrict__ o) {
    int win = blockIdx.x, h = blockIdx.y;
    int n = threadIdx.x;                       // token row 0..63
    __shared__ __align__(16) float sk[64][32];
    __shared__ __align__(16) float sv[64][32];
    __shared__ float sb[225];

    size_t base = ((size_t)win*64 + n)*768 + h*32;
    const float4* qp = (const float4*)(qkv + base);
    const float4* kp = (const float4*)(qkv + base + 256);
    const float4* vp = (const float4*)(qkv + base + 512);
    float qr[32];
#pragma unroll
    for (int q8 = 0; q8 < 8; q8++) {
        float4 tq = qp[q8];
        qr[q8*4+0]=tq.x; qr[q8*4+1]=tq.y; qr[q8*4+2]=tq.z; qr[q8*4+3]=tq.w;
        *(float4*)&sk[n][q8*4] = kp[q8];
        *(float4*)&sv[n][q8*4] = vp[q8];
    }
    for (int r = n; r < 225; r += 64) sb[r] = rel_bias[r*NH + h];
    __syncthreads();

    int i1 = n >> 3, j1 = n & 7;
    float s[64];
#pragma unroll 4
    for (int m = 0; m < 64; m++) {
        const float4* kr = (const float4*)sk[m];
        float d = 0.f;
#pragma unroll
        for (int q = 0; q < 8; q++) {
            float4 kv = kr[q];
            d = fmaf(qr[q*4+0], kv.x, d); d = fmaf(qr[q*4+1], kv.y, d);
            d = fmaf(qr[q*4+2], kv.z, d); d = fmaf(qr[q*4+3], kv.w, d);
        }
        int i2 = m >> 3, j2 = m & 7;
        s[m] = d * 0.17677669529663687f + sb[(i1-i2+7)*15 + (j1-j2+7)];
    }
    float mx = -1e30f;
#pragma unroll
    for (int m = 0; m < 64; m++) mx = fmaxf(mx, s[m]);
    float sum = 0.f;
#pragma unroll
    for (int m = 0; m < 64; m++) { s[m] = __expf(s[m]-mx); sum += s[m]; }
    float inv = 1.f / sum;
    float acc[32] = {};
#pragma unroll 4
    for (int m = 0; m < 64; m++) {
        float p = s[m] * inv;
        const float4* vr = (const float4*)sv[m];
#pragma unroll
        for (int q = 0; q < 8; q++) {
            float4 vv = vr[q];
            acc[q*4+0] = fmaf(p, vv.x, acc[q*4+0]);
            acc[q*4+1] = fmaf(p, vv.y, acc[q*4+1]);
            acc[q*4+2] = fmaf(p, vv.z, acc[q*4+2]);
            acc[q*4+3] = fmaf(p, vv.w, acc[q*4+3]);
        }
    }
    float* op = o + ((size_t)win*64 + n)*256 + h*32;
#pragma unroll
    for (int q = 0; q < 8; q++)
        *(float4*)(op + q*4) = make_float4(acc[q*4], acc[q*4+1], acc[q*4+2], acc[q*4+3]);
}

// -------------------- SE pooling + gate -------------------------------------
__global__ void __launch_bounds__(256) k_pool_partial(const float* __restrict__ y,
                                                      float* __restrict__ part) {
    size_t t0 = (size_t)blockIdx.x * 256;
    float s = 0.f;
#pragma unroll 4
    for (int i = 0; i < 256; i++) s += y[(t0 + i)*256 + threadIdx.x];
    part[blockIdx.x*256 + threadIdx.x] = s;
}

__global__ void __launch_bounds__(256) k_pool_gate(const float* __restrict__ part,
                                                   const float* __restrict__ w1,
                                                   const float* __restrict__ b1,
                                                   const float* __restrict__ w2,
                                                   const float* __restrict__ b2,
                                                   float* __restrict__ gate) {
    int b = blockIdx.x;
    float s = 0.f;
    for (int i = 0; i < 144; i++) s += part[(b*144 + i)*256 + threadIdx.x];
    float pooled = s * (1.f / (float)TOK_PER_B);
    __shared__ float sp[256];
    __shared__ float hid[16];
    sp[threadIdx.x] = pooled;
    __syncthreads();
    if (threadIdx.x < 16) {
        float a = b1[threadIdx.x];
        for (int c = 0; c < 256; c++) a = fmaf(sp[c], w1[c*16 + threadIdx.x], a);
        hid[threadIdx.x] = fmaxf(a, 0.f);
    }
    __syncthreads();
    float g = b2[threadIdx.x];
#pragma unroll
    for (int j = 0; j < 16; j++) g = fmaf(hid[j], w2[j*256 + threadIdx.x], g);
    gate[b*256 + threadIdx.x] = 1.f / (1.f + __expf(-g));
}

// ---------------------------------------------------------------------------
extern "C" void kernel_launch(void* const* d_in, const int* in_sizes, int n_in,
                              void* d_out, int out_size) {
    const float* x      = (const float*)d_in[0];
    const float* n1_g   = (const float*)d_in[1];
    const float* n1_b   = (const float*)d_in[2];
    const float* qkv_w  = (const float*)d_in[3];
    const float* qkv_b  = (const float*)d_in[4];
    const float* proj_w = (const float*)d_in[5];
    const float* proj_b = (const float*)d_in[6];
    const float* rel_b  = (const float*)d_in[7];
    const float* se_w1  = (const float*)d_in[8];
    const float* se_b1  = (const float*)d_in[9];
    const float* se_w2  = (const float*)d_in[10];
    const float* se_b2  = (const float*)d_in[11];
    const float* n3_g   = (const float*)d_in[12];
    const float* n3_b   = (const float*)d_in[13];
    const float* mlp_w1 = (const float*)d_in[14];
    const float* mlp_b1 = (const float*)d_in[15];
    const float* mlp_w2 = (const float*)d_in[16];
    const float* mlp_b2 = (const float*)d_in[17];
    float* out = (float*)d_out;

    float *wins, *hbuf, *big, *part, *gate;
    cudaGetSymbolAddress((void**)&wins, g_wins);
    cudaGetSymbolAddress((void**)&hbuf, g_h);
    cudaGetSymbolAddress((void**)&big,  g_big);
    cudaGetSymbolAddress((void**)&part, g_part);
    cudaGetSymbolAddress((void**)&gate, g_gate);

    dim3 b328(32, 8);
    dim3 gtr(WW_/32, HH, BATCH*8);

    // 1. window partition
    k_winpart<<<gtr, b328>>>(x, wins);
    // 2. LN1
    k_ln<<<NTOK/8, b328>>>(wins, n1_g, n1_b, hbuf);
    // 3. QKV GEMM -> big (stride 768)
    k_sgemm<<<dim3(NTOK/128, 768/64), 256>>>(hbuf, qkv_w, qkv_b, nullptr, big, 768, 256, 0);
    // 4. attention -> hbuf
    k_attn<<<dim3(NWIN, NH), 64>>>(big, rel_b, hbuf);
    // 5. proj + residual(wins) -> wins (y)
    k_sgemm<<<dim3(NTOK/128, 256/64), 256>>>(hbuf, proj_w, proj_b, wins, wins, 256, 256, 0);
    // 6-7. SE pooled gate
    k_pool_partial<<<576, 256>>>(wins, part);
    k_pool_gate<<<BATCH, 256>>>(part, se_w1, se_b1, se_w2, se_b2, gate);
    // 8. xf = y*gate (in place), hm = LN3(xf) -> hbuf
    k_gate_ln<<<NTOK/8, b328>>>(wins, gate, n3_g, n3_b, hbuf);
    // 9. MLP1 + GELU -> big (stride 1024)
    k_sgemm<<<dim3(NTOK/128, 1024/64), 256>>>(hbuf, mlp_w1, mlp_b1, nullptr, big, 1024, 256, 1);
    // 10. MLP2 + residual(xf) -> hbuf (final tokens)
    k_sgemm<<<dim3(NTOK/128, 256/64), 256>>>(big, mlp_w2, mlp_b2, wins, hbuf, 256, 1024, 0);
    // 11. window reverse -> out
    k_winrev<<<gtr, b328>>>(hbuf, out);
}

// round 3
// speedup vs baseline: 1.9376x; 1.9376x over previous
#include <cuda_runtime.h>
#include <cuda_bf16.h>
#include <cstdint>
#include <math.h>

// ---------------------------------------------------------------------------
// HATBlock: window attention + SE channel gate + MLP
// Round 3: GEMMs on tensor cores via mma.sync.m16n8k8.tf32 (fixed include)
// B=4, C=256, H=W=192, WS=8, NH=8, HD=32
// ---------------------------------------------------------------------------

#define BATCH 4
#define DIM   256
#define HH    192
#define WW_   192
#define WS    8
#define NWH   24
#define NWIN  (BATCH*NWH*NWH)   // 2304
#define NTOK  (NWIN*64)         // 147456
#define NH    8
#define HD    32
#define TOK_PER_B (HH*WW_)      // 36864

// -------------------- scratch (device globals; no runtime alloc) -----------
__device__ float g_wins[(size_t)NTOK*256];
__device__ float g_h   [(size_t)NTOK*256];
__device__ float g_big [(size_t)NTOK*1024];
__device__ float g_part[576*256];
__device__ float g_gate[BATCH*256];

__device__ __forceinline__ float gelu_exact(float x) {
    return 0.5f * x * (1.0f + erff(x * 0.70710678118654752f));
}

__device__ __forceinline__ float tf32r(float x) {
    unsigned int u;
    asm("cvt.rna.tf32.f32 %0, %1;" : "=r"(u) : "f"(x));
    return __uint_as_float(u);
}

__device__ __forceinline__ void mma_tf32(float* c, const unsigned int* a, const unsigned int* b) {
    asm volatile(
        "mma.sync.aligned.m16n8k8.row.col.f32.tf32.tf32.f32 "
        "{%0,%1,%2,%3},{%4,%5,%6,%7},{%8,%9},{%0,%1,%2,%3};"
        : "+f"(c[0]), "+f"(c[1]), "+f"(c[2]), "+f"(c[3])
        : "r"(a[0]), "r"(a[1]), "r"(a[2]), "r"(a[3]), "r"(b[0]), "r"(b[1]));
}

// -------------------- window partition: x[B,C,H,W] -> wins[t,c] ------------
__global__ void k_winpart(const float* __restrict__ x, float* __restrict__ wins) {
    int w0 = blockIdx.x * 32, hh = blockIdx.y;
    int b = blockIdx.z >> 3, c0 = (blockIdx.z & 7) * 32;
    __shared__ float tile[32][33];
    for (int cc = threadIdx.y; cc < 32; cc += 8)
        tile[cc][threadIdx.x] =
            x[(((size_t)b*256 + c0 + cc)*HH + hh)*WW_ + w0 + threadIdx.x];
    __syncthreads();
    int hw = hh >> 3, i = hh & 7;
    for (int wi = threadIdx.y; wi < 32; wi += 8) {
        int w = w0 + wi, ww = w >> 3, j = w & 7;
        size_t t = (((size_t)b*NWH + hw)*NWH + ww)*64 + i*8 + j;
        wins[t*256 + c0 + threadIdx.x] = tile[threadIdx.x][wi];
    }
}

// -------------------- window reverse: z[t,c] -> out[B,C,H,W] ---------------
__global__ void k_winrev(const float* __restrict__ z, float* __restrict__ out) {
    int w0 = blockIdx.x * 32, hh = blockIdx.y;
    int b = blockIdx.z >> 3, c0 = (blockIdx.z & 7) * 32;
    __shared__ float tile[32][33];
    int hw = hh >> 3, i = hh & 7;
    for (int wi = threadIdx.y; wi < 32; wi += 8) {
        int w = w0 + wi, ww = w >> 3, j = w & 7;
        size_t t = (((size_t)b*NWH + hw)*NWH + ww)*64 + i*8 + j;
        tile[wi][threadIdx.x] = z[t*256 + c0 + threadIdx.x];
    }
    __syncthreads();
    for (int cc = threadIdx.y; cc < 32; cc += 8)
        out[(((size_t)b*256 + c0 + cc)*HH + hh)*WW_ + w0 + threadIdx.x] =
            tile[threadIdx.x][cc];
}

// -------------------- row LayerNorm (one warp per 256-wide row) ------------
__global__ void __launch_bounds__(256) k_ln(const float* __restrict__ in,
                                            const float* __restrict__ g,
                                            const float* __restrict__ be,
                                            float* __restrict__ out) {
    int row = blockIdx.x * 8 + threadIdx.y;
    const float* p = in + (size_t)row * 256;
    float v[8], s = 0.f, s2 = 0.f;
#pragma unroll
    for (int k = 0; k < 8; k++) {
        v[k] = p[threadIdx.x + 32*k];
        s += v[k]; s2 += v[k]*v[k];
    }
#pragma unroll
    for (int o = 16; o; o >>= 1) {
        s  += __shfl_xor_sync(0xffffffffu, s,  o);
        s2 += __shfl_xor_sync(0xffffffffu, s2, o);
    }
    float mean = s * (1.f/256.f);
    float var  = s2 * (1.f/256.f) - mean*mean;
    float inv  = rsqrtf(var + 1e-5f);
    float* q = out + (size_t)row * 256;
#pragma unroll
    for (int k = 0; k < 8; k++) {
        int c = threadIdx.x + 32*k;
        q[c] = (v[k]-mean)*inv*g[c] + be[c];
    }
}

// -------------------- gate*y (in place) + LayerNorm -------------------------
__global__ void __launch_bounds__(256) k_gate_ln(float* __restrict__ y,
                                                 const float* __restrict__ gate,
                                                 const float* __restrict__ g,
                                                 const float* __restrict__ be,
                                                 float* __restrict__ hm) {
    int row = blockIdx.x * 8 + threadIdx.y;
    int b = row / TOK_PER_B;
    float* p = y + (size_t)row * 256;
    const float* gp = gate + b*256;
    float v[8], s = 0.f, s2 = 0.f;
#pragma unroll
    for (int k = 0; k < 8; k++) {
        int c = threadIdx.x + 32*k;
        float t = p[c] * gp[c];
        p[c] = t;
        v[k] = t; s += t; s2 += t*t;
    }
#pragma unroll
    for (int o = 16; o; o >>= 1) {
        s  += __shfl_xor_sync(0xffffffffu, s,  o);
        s2 += __shfl_xor_sync(0xffffffffu, s2, o);
    }
    float mean = s * (1.f/256.f);
    float var  = s2 * (1.f/256.f) - mean*mean;
    float inv  = rsqrtf(var + 1e-5f);
    float* q = hm + (size_t)row * 256;
#pragma unroll
    for (int k = 0; k < 8; k++) {
        int c = threadIdx.x + 32*k;
        q[c] = (v[k]-mean)*inv*g[c] + be[c];
    }
}

// -------------------- TF32 tensor-core GEMM --------------------------------
// C = act(A @ W + bias [+ R]);  A [M,K] rm fp32, W [K,N] rm fp32, C/R [M,N].
// Block tile 128x128x16, 256 threads = 8 warps (4 M x 2 N), warp tile 32x64.
#define ASTR 20
#define BSTR 132
__global__ void __launch_bounds__(256) k_mma_gemm(const float* __restrict__ A,
                                                  const float* __restrict__ W,
                                                  const float* __restrict__ bias,
                                                  const float* __restrict__ R,
                                                  float* __restrict__ C,
                                                  int N, int K, int act) {
    __shared__ __align__(16) float As[2][128][ASTR];
    __shared__ __align__(16) float Bs[2][16][BSTR];

    const int m0 = blockIdx.x * 128, n0 = blockIdx.y * 128;
    const int tid  = threadIdx.x;
    const int lane = tid & 31;
    const int wid  = tid >> 5;
    const int wm   = wid & 3;        // warp row (0..3) -> 32 rows
    const int wn   = wid >> 2;       // warp col (0..1) -> 64 cols
    const int g    = lane >> 2;      // group id 0..7
    const int tig  = lane & 3;       // thread in group 0..3

    const int am = tid >> 2;               // 0..63 (rows am, am+64)
    const int ak = (tid & 3) * 4;          // k offset 0,4,8,12
    const int bk = tid >> 5;               // 0..7 (rows bk, bk+8)
    const int bn = (tid & 31) * 4;         // 0..124

    const float* Ap = A + (size_t)(m0 + am) * K + ak;
    const float* Bp = W + (size_t)bk * N + n0 + bn;

    const int KT = K / 16;
    float4 ra0, ra1, rb0, rb1;

    ra0 = *(const float4*)(Ap);
    ra1 = *(const float4*)(Ap + (size_t)64 * K);
    rb0 = *(const float4*)(Bp);
    rb1 = *(const float4*)(Bp + (size_t)8 * N);

    *(float4*)&As[0][am     ][ak] = make_float4(tf32r(ra0.x), tf32r(ra0.y), tf32r(ra0.z), tf32r(ra0.w));
    *(float4*)&As[0][am + 64][ak] = make_float4(tf32r(ra1.x), tf32r(ra1.y), tf32r(ra1.z), tf32r(ra1.w));
    *(float4*)&Bs[0][bk    ][bn] = make_float4(tf32r(rb0.x), tf32r(rb0.y), tf32r(rb0.z), tf32r(rb0.w));
    *(float4*)&Bs[0][bk + 8][bn] = make_float4(tf32r(rb1.x), tf32r(rb1.y), tf32r(rb1.z), tf32r(rb1.w));
    __syncthreads();

    float acc[2][8][4];
#pragma unroll
    for (int i = 0; i < 2; i++)
#pragma unroll
        for (int j = 0; j < 8; j++)
#pragma unroll
            for (int q = 0; q < 4; q++) acc[i][j][q] = 0.f;

    const int arow = wm * 32;
    const int bcol = wn * 64;

    for (int kt = 0; kt < KT; kt++) {
        const int cur = kt & 1;
        if (kt + 1 < KT) {
            const float* Ap2 = Ap + (size_t)(kt + 1) * 16;
            const float* Bp2 = Bp + (size_t)(kt + 1) * 16 * N;
            ra0 = *(const float4*)(Ap2);
            ra1 = *(const float4*)(Ap2 + (size_t)64 * K);
            rb0 = *(const float4*)(Bp2);
            rb1 = *(const float4*)(Bp2 + (size_t)8 * N);
        }
#pragma unroll
        for (int ks = 0; ks < 2; ks++) {
            unsigned int afr[2][4], bfr[8][2];
#pragma unroll
            for (int mt = 0; mt < 2; mt++) {
                int r = arow + mt*16 + g;
                afr[mt][0] = __float_as_uint(As[cur][r    ][ks*8 + tig]);
                afr[mt][1] = __float_as_uint(As[cur][r + 8][ks*8 + tig]);
                afr[mt][2] = __float_as_uint(As[cur][r    ][ks*8 + tig + 4]);
                afr[mt][3] = __float_as_uint(As[cur][r + 8][ks*8 + tig + 4]);
            }
#pragma unroll
            for (int nt = 0; nt < 8; nt++) {
                int cc = bcol + nt*8 + g;
                bfr[nt][0] = __float_as_uint(Bs[cur][ks*8 + tig    ][cc]);
                bfr[nt][1] = __float_as_uint(Bs[cur][ks*8 + tig + 4][cc]);
            }
#pragma unroll
            for (int mt = 0; mt < 2; mt++)
#pragma unroll
                for (int nt = 0; nt < 8; nt++)
                    mma_tf32(acc[mt][nt], afr[mt], bfr[nt]);
        }
        if (kt + 1 < KT) {
            const int nxt = cur ^ 1;
            *(float4*)&As[nxt][am     ][ak] = make_float4(tf32r(ra0.x), tf32r(ra0.y), tf32r(ra0.z), tf32r(ra0.w));
            *(float4*)&As[nxt][am + 64][ak] = make_float4(tf32r(ra1.x), tf32r(ra1.y), tf32r(ra1.z), tf32r(ra1.w));
            *(float4*)&Bs[nxt][bk    ][bn] = make_float4(tf32r(rb0.x), tf32r(rb0.y), tf32r(rb0.z), tf32r(rb0.w));
            *(float4*)&Bs[nxt][bk + 8][bn] = make_float4(tf32r(rb1.x), tf32r(rb1.y), tf32r(rb1.z), tf32r(rb1.w));
            __syncthreads();
        }
    }

    // epilogue
#pragma unroll
    for (int nt = 0; nt < 8; nt++) {
        int col = n0 + bcol + nt*8 + 2*tig;
        float b0 = bias[col], b1 = bias[col + 1];
#pragma unroll
        for (int mt = 0; mt < 2; mt++) {
            size_t r0 = (size_t)m0 + arow + mt*16 + g;
            size_t r1 = r0 + 8;
            float v00 = acc[mt][nt][0] + b0, v01 = acc[mt][nt][1] + b1;
            float v10 = acc[mt][nt][2] + b0, v11 = acc[mt][nt][3] + b1;
            if (R) {
                const float2 q0 = *(const float2*)(R + r0*N + col);
                const float2 q1 = *(const float2*)(R + r1*N + col);
                v00 += q0.x; v01 += q0.y; v10 += q1.x; v11 += q1.y;
            }
            if (act) {
                v00 = gelu_exact(v00); v01 = gelu_exact(v01);
                v10 = gelu_exact(v10); v11 = gelu_exact(v11);
            }
            *(float2*)(C + r0*N + col) = make_float2(v00, v01);
            *(float2*)(C + r1*N + col) = make_float2(v10, v11);
        }
    }
}

// -------------------- window attention: one CTA per (window, head) ---------
__global__ void __launch_bounds__(64) k_attn(const float* __restrict__ qkv,
                                             const float* __restrict__ rel_bias,
                                             float* __restrict__ o) {
    int win = blockIdx.x, h = blockIdx.y;
    int n = threadIdx.x;
    __shared__ __align__(16) float sk[64][32];
    __shared__ __align__(16) float sv[64][32];
    __shared__ float sb[225];

    size_t base = ((size_t)win*64 + n)*768 + h*32;
    const float4* qp = (const float4*)(qkv + base);
    const float4* kp = (const float4*)(qkv + base + 256);
    const float4* vp = (const float4*)(qkv + base + 512);
    float qr[32];
#pragma unroll
    for (int q8 = 0; q8 < 8; q8++) {
        float4 tq = qp[q8];
        qr[q8*4+0]=tq.x; qr[q8*4+1]=tq.y; qr[q8*4+2]=tq.z; qr[q8*4+3]=tq.w;
        *(float4*)&sk[n][q8*4] = kp[q8];
        *(float4*)&sv[n][q8*4] = vp[q8];
    }
    for (int r = n; r < 225; r += 64) sb[r] = rel_bias[r*NH + h];
    __syncthreads();

    int i1 = n >> 3, j1 = n & 7;
    float s[64];
#pragma unroll 4
    for (int m = 0; m < 64; m++) {
        const float4* kr = (const float4*)sk[m];
        float d = 0.f;
#pragma unroll
        for (int q = 0; q < 8; q++) {
            float4 kv = kr[q];
            d = fmaf(qr[q*4+0], kv.x, d); d = fmaf(qr[q*4+1], kv.y, d);
            d = fmaf(qr[q*4+2], kv.z, d); d = fmaf(qr[q*4+3], kv.w, d);
        }
        int i2 = m >> 3, j2 = m & 7;
        s[m] = d * 0.17677669529663687f + sb[(i1-i2+7)*15 + (j1-j2+7)];
    }
    float mx = -1e30f;
#pragma unroll
    for (int m = 0; m < 64; m++) mx = fmaxf(mx, s[m]);
    float sum = 0.f;
#pragma unroll
    for (int m = 0; m < 64; m++) { s[m] = __expf(s[m]-mx); sum += s[m]; }
    float inv = 1.f / sum;
    float acc[32] = {};
#pragma unroll 4
    for (int m = 0; m < 64; m++) {
        float p = s[m] * inv;
        const float4* vr = (const float4*)sv[m];
#pragma unroll
        for (int q = 0; q < 8; q++) {
            float4 vv = vr[q];
            acc[q*4+0] = fmaf(p, vv.x, acc[q*4+0]);
            acc[q*4+1] = fmaf(p, vv.y, acc[q*4+1]);
            acc[q*4+2] = fmaf(p, vv.z, acc[q*4+2]);
            acc[q*4+3] = fmaf(p, vv.w, acc[q*4+3]);
        }
    }
    float* op = o + ((size_t)win*64 + n)*256 + h*32;
#pragma unroll
    for (int q = 0; q < 8; q++)
        *(float4*)(op + q*4) = make_float4(acc[q*4], acc[q*4+1], acc[q*4+2], acc[q*4+3]);
}

// -------------------- SE pooling + gate -------------------------------------
__global__ void __launch_bounds__(256) k_pool_partial(const float* __restrict__ y,
                                                      float* __restrict__ part) {
    size_t t0 = (size_t)blockIdx.x * 256;
    float s = 0.f;
#pragma unroll 4
    for (int i = 0; i < 256; i++) s += y[(t0 + i)*256 + threadIdx.x];
    part[blockIdx.x*256 + threadIdx.x] = s;
}

__global__ void __launch_bounds__(256) k_pool_gate(const float* __restrict__ part,
                                                   const float* __restrict__ w1,
                                                   const float* __restrict__ b1,
                                                   const float* __restrict__ w2,
                                                   const float* __restrict__ b2,
                                                   float* __restrict__ gate) {
    int b = blockIdx.x;
    float s = 0.f;
    for (int i = 0; i < 144; i++) s += part[(b*144 + i)*256 + threadIdx.x];
    float pooled = s * (1.f / (float)TOK_PER_B);
    __shared__ float sp[256];
    __shared__ float hid[16];
    sp[threadIdx.x] = pooled;
    __syncthreads();
    if (threadIdx.x < 16) {
        float a = b1[threadIdx.x];
        for (int c = 0; c < 256; c++) a = fmaf(sp[c], w1[c*16 + threadIdx.x], a);
        hid[threadIdx.x] = fmaxf(a, 0.f);
    }
    __syncthreads();
    float g = b2[threadIdx.x];
#pragma unroll
    for (int j = 0; j < 16; j++) g = fmaf(hid[j], w2[j*256 + threadIdx.x], g);
    gate[b*256 + threadIdx.x] = 1.f / (1.f + __expf(-g));
}

// ---------------------------------------------------------------------------
extern "C" void kernel_launch(void* const* d_in, const int* in_sizes, int n_in,
                              void* d_out, int out_size) {
    const float* x      = (const float*)d_in[0];
    const float* n1_g   = (const float*)d_in[1];
    const float* n1_b   = (const float*)d_in[2];
    const float* qkv_w  = (const float*)d_in[3];
    const float* qkv_b  = (const float*)d_in[4];
    const float* proj_w = (const float*)d_in[5];
    const float* proj_b = (const float*)d_in[6];
    const float* rel_b  = (const float*)d_in[7];
    const float* se_w1  = (const float*)d_in[8];
    const float* se_b1  = (const float*)d_in[9];
    const float* se_w2  = (const float*)d_in[10];
    const float* se_b2  = (const float*)d_in[11];
    const float* n3_g   = (const float*)d_in[12];
    const float* n3_b   = (const float*)d_in[13];
    const float* mlp_w1 = (const float*)d_in[14];
    const float* mlp_b1 = (const float*)d_in[15];
    const float* mlp_w2 = (const float*)d_in[16];
    const float* mlp_b2 = (const float*)d_in[17];
    float* out = (float*)d_out;

    float *wins, *hbuf, *big, *part, *gate;
    cudaGetSymbolAddress((void**)&wins, g_wins);
    cudaGetSymbolAddress((void**)&hbuf, g_h);
    cudaGetSymbolAddress((void**)&big,  g_big);
    cudaGetSymbolAddress((void**)&part, g_part);
    cudaGetSymbolAddress((void**)&gate, g_gate);

    dim3 b328(32, 8);
    dim3 gtr(WW_/32, HH, BATCH*8);

    // 1. window partition
    k_winpart<<<gtr, b328>>>(x, wins);
    // 2. LN1
    k_ln<<<NTOK/8, b328>>>(wins, n1_g, n1_b, hbuf);
    // 3. QKV GEMM -> big (stride 768)
    k_mma_gemm<<<dim3(NTOK/128, 768/128), 256>>>(hbuf, qkv_w, qkv_b, nullptr, big, 768, 256, 0);
    // 4. attention -> hbuf
    k_attn<<<dim3(NWIN, NH), 64>>>(big, rel_b, hbuf);
    // 5. proj + residual(wins) -> wins (y)
    k_mma_gemm<<<dim3(NTOK/128, 256/128), 256>>>(hbuf, proj_w, proj_b, wins, wins, 256, 256, 0);
    // 6-7. SE pooled gate
    k_pool_partial<<<576, 256>>>(wins, part);
    k_pool_gate<<<BATCH, 256>>>(part, se_w1, se_b1, se_w2, se_b2, gate);
    // 8. xf = y*gate (in place), hm = LN3(xf) -> hbuf
    k_gate_ln<<<NTOK/8, b328>>>(wins, gate, n3_g, n3_b, hbuf);
    // 9. MLP1 + GELU -> big (stride 1024)
    k_mma_gemm<<<dim3(NTOK/128, 1024/128), 256>>>(hbuf, mlp_w1, mlp_b1, nullptr, big, 1024, 256, 1);
    // 10. MLP2 + residual(xf) -> hbuf (final tokens)
    k_mma_gemm<<<dim3(NTOK/128, 256/128), 256>>>(big, mlp_w2, mlp_b2, wins, hbuf, 256, 1024, 0);
    // 11. window reverse -> out
    k_winrev<<<gtr, b328>>>(hbuf, out);
}

// round 4
// speedup vs baseline: 2.4237x; 1.2509x over previous
#include <cuda_runtime.h>
#include <cuda_bf16.h>
#include <cstdint>
#include <math.h>

// ---------------------------------------------------------------------------
// HATBlock: window attention + SE channel gate + MLP
// Round 4: cp.async 3-stage tf32 GEMM (64x64 warp tile), f32x2 attention,
//          pre-rounded tf32 weights.
// B=4, C=256, H=W=192, WS=8, NH=8, HD=32
// ---------------------------------------------------------------------------

#define BATCH 4
#define DIM   256
#define HH    192
#define WW_   192
#define WS    8
#define NWH   24
#define NWIN  (BATCH*NWH*NWH)   // 2304
#define NTOK  (NWIN*64)         // 147456
#define NH    8
#define HD    32
#define TOK_PER_B (HH*WW_)      // 36864

typedef unsigned long long u64;

// -------------------- scratch (device globals; no runtime alloc) -----------
__device__ float g_wins[(size_t)NTOK*256];
__device__ float g_h   [(size_t)NTOK*256];
__device__ float g_big [(size_t)NTOK*1024];
__device__ float g_part[576*256];
__device__ float g_gate[BATCH*256];
__device__ float g_wrnd[786432];   // tf32-rounded weights

__device__ __forceinline__ float gelu_exact(float x) {
    return 0.5f * x * (1.0f + erff(x * 0.70710678118654752f));
}

__device__ __forceinline__ float tf32r(float x) {
    unsigned int u;
    asm("cvt.rna.tf32.f32 %0, %1;" : "=r"(u) : "f"(x));
    return __uint_as_float(u);
}

__device__ __forceinline__ void mma_tf32(float* c, const unsigned int* a, const unsigned int* b) {
    asm volatile(
        "mma.sync.aligned.m16n8k8.row.col.f32.tf32.tf32.f32 "
        "{%0,%1,%2,%3},{%4,%5,%6,%7},{%8,%9},{%0,%1,%2,%3};"
        : "+f"(c[0]), "+f"(c[1]), "+f"(c[2]), "+f"(c[3])
        : "r"(a[0]), "r"(a[1]), "r"(a[2]), "r"(a[3]), "r"(b[0]), "r"(b[1]));
}

__device__ __forceinline__ void cp_async16(void* smem, const void* gmem) {
    unsigned s = (unsigned)__cvta_generic_to_shared(smem);
    asm volatile("cp.async.ca.shared.global [%0], [%1], 16;" :: "r"(s), "l"(gmem));
}
__device__ __forceinline__ void cp_commit() { asm volatile("cp.async.commit_group;"); }
__device__ __forceinline__ void cp_wait1()  { asm volatile("cp.async.wait_group 1;"); }

// packed fp32x2 helpers
__device__ __forceinline__ u64 pk2(float a, float b) {
    u64 r; asm("mov.b64 %0, {%1,%2};" : "=l"(r) : "f"(a), "f"(b)); return r;
}
__device__ __forceinline__ void upk2(u64 v, float& a, float& b) {
    asm("mov.b64 {%0,%1}, %2;" : "=f"(a), "=f"(b) : "l"(v));
}
__device__ __forceinline__ u64 fma2(u64 a, u64 b, u64 c) {
    u64 d; asm("fma.rn.f32x2 %0, %1, %2, %3;" : "=l"(d) : "l"(a), "l"(b), "l"(c)); return d;
}
__device__ __forceinline__ u64 mul2(u64 a, u64 b) {
    u64 d; asm("mul.rn.f32x2 %0, %1, %2;" : "=l"(d) : "l"(a), "l"(b)); return d;
}

// -------------------- tf32 rounding copy ------------------------------------
__global__ void k_round(const float* __restrict__ in, float* __restrict__ out, int n) {
    int i = (blockIdx.x * 256 + threadIdx.x) * 4;
    if (i < n) {
        float4 v = *(const float4*)(in + i);
        *(float4*)(out + i) = make_float4(tf32r(v.x), tf32r(v.y), tf32r(v.z), tf32r(v.w));
    }
}

// -------------------- window partition: x[B,C,H,W] -> wins[t,c] ------------
__global__ void k_winpart(const float* __restrict__ x, float* __restrict__ wins) {
    int w0 = blockIdx.x * 32, hh = blockIdx.y;
    int b = blockIdx.z >> 3, c0 = (blockIdx.z & 7) * 32;
    __shared__ float tile[32][33];
    for (int cc = threadIdx.y; cc < 32; cc += 8)
        tile[cc][threadIdx.x] =
            x[(((size_t)b*256 + c0 + cc)*HH + hh)*WW_ + w0 + threadIdx.x];
    __syncthreads();
    int hw = hh >> 3, i = hh & 7;
    for (int wi = threadIdx.y; wi < 32; wi += 8) {
        int w = w0 + wi, ww = w >> 3, j = w & 7;
        size_t t = (((size_t)b*NWH + hw)*NWH + ww)*64 + i*8 + j;
        wins[t*256 + c0 + threadIdx.x] = tile[threadIdx.x][wi];
    }
}

// -------------------- window reverse: z[t,c] -> out[B,C,H,W] ---------------
__global__ void k_winrev(const float* __restrict__ z, float* __restrict__ out) {
    int w0 = blockIdx.x * 32, hh = blockIdx.y;
    int b = blockIdx.z >> 3, c0 = (blockIdx.z & 7) * 32;
    __shared__ float tile[32][33];
    int hw = hh >> 3, i = hh & 7;
    for (int wi = threadIdx.y; wi < 32; wi += 8) {
        int w = w0 + wi, ww = w >> 3, j = w & 7;
        size_t t = (((size_t)b*NWH + hw)*NWH + ww)*64 + i*8 + j;
        tile[wi][threadIdx.x] = z[t*256 + c0 + threadIdx.x];
    }
    __syncthreads();
    for (int cc = threadIdx.y; cc < 32; cc += 8)
        out[(((size_t)b*256 + c0 + cc)*HH + hh)*WW_ + w0 + threadIdx.x] =
            tile[threadIdx.x][cc];
}

// -------------------- row LayerNorm (tf32-rounded output) ------------------
__global__ void __launch_bounds__(256) k_ln(const float* __restrict__ in,
                                            const float* __restrict__ g,
                                            const float* __restrict__ be,
                                            float* __restrict__ out) {
    int row = blockIdx.x * 8 + threadIdx.y;
    const float* p = in + (size_t)row * 256;
    float v[8], s = 0.f, s2 = 0.f;
#pragma unroll
    for (int k = 0; k < 8; k++) {
        v[k] = p[threadIdx.x + 32*k];
        s += v[k]; s2 += v[k]*v[k];
    }
#pragma unroll
    for (int o = 16; o; o >>= 1) {
        s  += __shfl_xor_sync(0xffffffffu, s,  o);
        s2 += __shfl_xor_sync(0xffffffffu, s2, o);
    }
    float mean = s * (1.f/256.f);
    float var  = s2 * (1.f/256.f) - mean*mean;
    float inv  = rsqrtf(var + 1e-5f);
    float* q = out + (size_t)row * 256;
#pragma unroll
    for (int k = 0; k < 8; k++) {
        int c = threadIdx.x + 32*k;
        q[c] = tf32r((v[k]-mean)*inv*g[c] + be[c]);
    }
}

// -------------------- gate*y (in place) + LayerNorm (rounded) --------------
__global__ void __launch_bounds__(256) k_gate_ln(float* __restrict__ y,
                                                 const float* __restrict__ gate,
                                                 const float* __restrict__ g,
                                                 const float* __restrict__ be,
                                                 float* __restrict__ hm) {
    int row = blockIdx.x * 8 + threadIdx.y;
    int b = row / TOK_PER_B;
    float* p = y + (size_t)row * 256;
    const float* gp = gate + b*256;
    float v[8], s = 0.f, s2 = 0.f;
#pragma unroll
    for (int k = 0; k < 8; k++) {
        int c = threadIdx.x + 32*k;
        float t = p[c] * gp[c];
        p[c] = t;
        v[k] = t; s += t; s2 += t*t;
    }
#pragma unroll
    for (int o = 16; o; o >>= 1) {
        s  += __shfl_xor_sync(0xffffffffu, s,  o);
        s2 += __shfl_xor_sync(0xffffffffu, s2, o);
    }
    float mean = s * (1.f/256.f);
    float var  = s2 * (1.f/256.f) - mean*mean;
    float inv  = rsqrtf(var + 1e-5f);
    float* q = hm + (size_t)row * 256;
#pragma unroll
    for (int k = 0; k < 8; k++) {
        int c = threadIdx.x + 32*k;
        q[c] = tf32r((v[k]-mean)*inv*g[c] + be[c]);
    }
}

// -------------------- TF32 tensor-core GEMM (cp.async, 3-stage) ------------
// C = act(A @ W + bias [+ R]); A [M,K], W [K,N] both pre-rounded to tf32.
// Block tile 128x128x16, 128 threads = 4 warps (2x2), warp tile 64x64.
#define STAGES 3
#define ASTR 20
#define BSTR 136
__global__ void __launch_bounds__(128, 2) k_mma_gemm(const float* __restrict__ A,
                                                     const float* __restrict__ W,
                                                     const float* __restrict__ bias,
                                                     const float* __restrict__ R,
                                                     float* __restrict__ C,
                                                     int N, int K, int act) {
    __shared__ __align__(16) float As[STAGES][128][ASTR];
    __shared__ __align__(16) float Bs[STAGES][16][BSTR];

    const int m0 = blockIdx.x * 128, n0 = blockIdx.y * 128;
    const int tid  = threadIdx.x;
    const int lane = tid & 31;
    const int wid  = tid >> 5;
    const int wm   = wid & 1;        // 64 rows each
    const int wn   = wid >> 1;       // 64 cols each
    const int g    = lane >> 2;
    const int tig  = lane & 3;

    // gmem->smem mapping (cp.async 16B)
    const int arow_ld = tid >> 2;          // 0..31 (+32i)
    const int akc     = (tid & 3) * 4;     // 0,4,8,12

    const int KT = K / 16;

    // stage loaders
    auto load_stage = [&](int s, int kt) {
        const float* Ag = A + (size_t)(m0 + arow_ld) * K + kt*16 + akc;
#pragma unroll
        for (int i = 0; i < 4; i++)
            cp_async16(&As[s][arow_ld + 32*i][akc], Ag + (size_t)(32*i) * K);
        const float* Wg = W + (size_t)(kt*16) * N + n0;
#pragma unroll
        for (int i = 0; i < 4; i++) {
            int c = tid + 128*i;
            int br = c >> 5, bc = (c & 31) * 4;
            cp_async16(&Bs[s][br][bc], Wg + (size_t)br * N + bc);
        }
    };

    load_stage(0, 0); cp_commit();
    load_stage(1, 1); cp_commit();

    float acc[4][8][4];
#pragma unroll
    for (int i = 0; i < 4; i++)
#pragma unroll
        for (int j = 0; j < 8; j++)
#pragma unroll
            for (int q = 0; q < 4; q++) acc[i][j][q] = 0.f;

    const int arow = wm * 64;
    const int bcol = wn * 64;

    for (int kt = 0; kt < KT; kt++) {
        cp_wait1();
        __syncthreads();
        if (kt + 2 < KT) load_stage((kt + 2) % STAGES, kt + 2);
        cp_commit();
        const int cur = kt % STAGES;
#pragma unroll
        for (int ks = 0; ks < 2; ks++) {
            unsigned int afr[4][4], bfr[8][2];
#pragma unroll
            for (int mt = 0; mt < 4; mt++) {
                int r = arow + mt*16 + g;
                afr[mt][0] = __float_as_uint(As[cur][r    ][ks*8 + tig]);
                afr[mt][1] = __float_as_uint(As[cur][r + 8][ks*8 + tig]);
                afr[mt][2] = __float_as_uint(As[cur][r    ][ks*8 + tig + 4]);
                afr[mt][3] = __float_as_uint(As[cur][r + 8][ks*8 + tig + 4]);
            }
#pragma unroll
            for (int nt = 0; nt < 8; nt++) {
                int cc = bcol + nt*8 + g;
                bfr[nt][0] = __float_as_uint(Bs[cur][ks*8 + tig    ][cc]);
                bfr[nt][1] = __float_as_uint(Bs[cur][ks*8 + tig + 4][cc]);
            }
#pragma unroll
            for (int mt = 0; mt < 4; mt++)
#pragma unroll
                for (int nt = 0; nt < 8; nt++)
                    mma_tf32(acc[mt][nt], afr[mt], bfr[nt]);
        }
    }

    // epilogue
#pragma unroll
    for (int nt = 0; nt < 8; nt++) {
        int col = n0 + bcol + nt*8 + 2*tig;
        float b0 = bias[col], b1 = bias[col + 1];
#pragma unroll
        for (int mt = 0; mt < 4; mt++) {
            size_t r0 = (size_t)m0 + arow + mt*16 + g;
            size_t r1 = r0 + 8;
            float v00 = acc[mt][nt][0] + b0, v01 = acc[mt][nt][1] + b1;
            float v10 = acc[mt][nt][2] + b0, v11 = acc[mt][nt][3] + b1;
            if (R) {
                const float2 q0 = *(const float2*)(R + r0*N + col);
                const float2 q1 = *(const float2*)(R + r1*N + col);
                v00 += q0.x; v01 += q0.y; v10 += q1.x; v11 += q1.y;
            }
            if (act) {
                v00 = tf32r(gelu_exact(v00)); v01 = tf32r(gelu_exact(v01));
                v10 = tf32r(gelu_exact(v10)); v11 = tf32r(gelu_exact(v11));
            }
            *(float2*)(C + r0*N + col) = make_float2(v00, v01);
            *(float2*)(C + r1*N + col) = make_float2(v10, v11);
        }
    }
}

// -------------------- window attention: f32x2 + chunked softmax ------------
__global__ void __launch_bounds__(64, 8) k_attn(const float* __restrict__ qkv,
                                                const float* __restrict__ rel_bias,
                                                float* __restrict__ o) {
    int win = blockIdx.x, h = blockIdx.y;
    int n = threadIdx.x;
    __shared__ __align__(16) float sk[64][32];
    __shared__ __align__(16) float sv[64][32];
    __shared__ float sb[225];

    size_t base = ((size_t)win*64 + n)*768 + h*32;
    const float4* qp = (const float4*)(qkv + base);
    const float4* kp = (const float4*)(qkv + base + 256);
    const float4* vp = (const float4*)(qkv + base + 512);
    u64 qr2[16];
#pragma unroll
    for (int q8 = 0; q8 < 8; q8++) {
        float4 tq = qp[q8];
        qr2[2*q8]   = pk2(tq.x, tq.y);
        qr2[2*q8+1] = pk2(tq.z, tq.w);
        *(float4*)&sk[n][q8*4] = kp[q8];
        *(float4*)&sv[n][q8*4] = vp[q8];
    }
    for (int r = n; r < 225; r += 64) sb[r] = rel_bias[r*NH + h];
    __syncthreads();

    const int i1 = n >> 3, j1 = n & 7;
    u64 acc2[16];
#pragma unroll
    for (int q = 0; q < 16; q++) acc2[q] = 0ull;
    float mx = -1e30f, sum = 0.f;
    float s[32];

#pragma unroll
    for (int chunk = 0; chunk < 2; chunk++) {
        const int mbase = chunk * 32;
#pragma unroll 4
        for (int mm = 0; mm < 32; mm++) {
            int m = mbase + mm;
            const float4* kr = (const float4*)sk[m];
            u64 da = 0ull, db = 0ull;
#pragma unroll
            for (int q8 = 0; q8 < 8; q8++) {
                float4 kv = kr[q8];
                da = fma2(qr2[2*q8],   pk2(kv.x, kv.y), da);
                db = fma2(qr2[2*q8+1], pk2(kv.z, kv.w), db);
            }
            float a, b, c, d;
            upk2(da, a, b); upk2(db, c, d);
            int i2 = m >> 3, j2 = m & 7;
            s[mm] = (a+b+c+d) * 0.17677669529663687f + sb[(i1-i2+7)*15 + (j1-j2+7)];
        }
        float cmx = -1e30f;
#pragma unroll
        for (int mm = 0; mm < 32; mm++) cmx = fmaxf(cmx, s[mm]);
        float M = fmaxf(mx, cmx);
        float f = __expf(mx - M);
        sum *= f;
        u64 f2 = pk2(f, f);
#pragma unroll
        for (int q = 0; q < 16; q++) acc2[q] = mul2(acc2[q], f2);
#pragma unroll 4
        for (int mm = 0; mm < 32; mm++) {
            int m = mbase + mm;
            float p = __expf(s[mm] - M);
            sum += p;
            u64 p2 = pk2(p, p);
            const float4* vr = (const float4*)sv[m];
#pragma unroll
            for (int q8 = 0; q8 < 8; q8++) {
                float4 vv = vr[q8];
                acc2[2*q8]   = fma2(p2, pk2(vv.x, vv.y), acc2[2*q8]);
                acc2[2*q8+1] = fma2(p2, pk2(vv.z, vv.w), acc2[2*q8+1]);
            }
        }
        mx = M;
    }

    float inv = 1.f / sum;
    float* op = o + ((size_t)win*64 + n)*256 + h*32;
#pragma unroll
    for (int q = 0; q < 16; q++) {
        float a, b;
        upk2(acc2[q], a, b);
        *(float2*)(op + 2*q) = make_float2(tf32r(a*inv), tf32r(b*inv));
    }
}

// -------------------- SE pooling + gate -------------------------------------
__global__ void __launch_bounds__(256) k_pool_partial(const float* __restrict__ y,
                                                      float* __restrict__ part) {
    size_t t0 = (size_t)blockIdx.x * 256;
    float s = 0.f;
#pragma unroll 4
    for (int i = 0; i < 256; i++) s += y[(t0 + i)*256 + threadIdx.x];
    part[blockIdx.x*256 + threadIdx.x] = s;
}

__global__ void __launch_bounds__(256) k_pool_gate(const float* __restrict__ part,
                                                   const float* __restrict__ w1,
                                                   const float* __restrict__ b1,
                                                   const float* __restrict__ w2,
                                                   const float* __restrict__ b2,
                                                   float* __restrict__ gate) {
    int b = blockIdx.x;
    float s = 0.f;
    for (int i = 0; i < 144; i++) s += part[(b*144 + i)*256 + threadIdx.x];
    float pooled = s * (1.f / (float)TOK_PER_B);
    __shared__ float sp[256];
    __shared__ float hid[16];
    sp[threadIdx.x] = pooled;
    __syncthreads();
    if (threadIdx.x < 16) {
        float a = b1[threadIdx.x];
        for (int c = 0; c < 256; c++) a = fmaf(sp[c], w1[c*16 + threadIdx.x], a);
        hid[threadIdx.x] = fmaxf(a, 0.f);
    }
    __syncthreads();
    float g = b2[threadIdx.x];
#pragma unroll
    for (int j = 0; j < 16; j++) g = fmaf(hid[j], w2[j*256 + threadIdx.x], g);
    gate[b*256 + threadIdx.x] = 1.f / (1.f + __expf(-g));
}

// ---------------------------------------------------------------------------
extern "C" void kernel_launch(void* const* d_in, const int* in_sizes, int n_in,
                              void* d_out, int out_size) {
    const float* x      = (const float*)d_in[0];
    const float* n1_g   = (const float*)d_in[1];
    const float* n1_b   = (const float*)d_in[2];
    const float* qkv_w  = (const float*)d_in[3];
    const float* qkv_b  = (const float*)d_in[4];
    const float* proj_w = (const float*)d_in[5];
    const float* proj_b = (const float*)d_in[6];
    const float* rel_b  = (const float*)d_in[7];
    const float* se_w1  = (const float*)d_in[8];
    const float* se_b1  = (const float*)d_in[9];
    const float* se_w2  = (const float*)d_in[10];
    const float* se_b2  = (const float*)d_in[11];
    const float* n3_g   = (const float*)d_in[12];
    const float* n3_b   = (const float*)d_in[13];
    const float* mlp_w1 = (const float*)d_in[14];
    const float* mlp_b1 = (const float*)d_in[15];
    const float* mlp_w2 = (const float*)d_in[16];
    const float* mlp_b2 = (const float*)d_in[17];
    float* out = (float*)d_out;

    float *wins, *hbuf, *big, *part, *gate, *wrnd;
    cudaGetSymbolAddress((void**)&wins, g_wins);
    cudaGetSymbolAddress((void**)&hbuf, g_h);
    cudaGetSymbolAddress((void**)&big,  g_big);
    cudaGetSymbolAddress((void**)&part, g_part);
    cudaGetSymbolAddress((void**)&gate, g_gate);
    cudaGetSymbolAddress((void**)&wrnd, g_wrnd);

    float* qkv_wr  = wrnd;            // 196608
    float* proj_wr = wrnd + 196608;   // 65536
    float* mlp_w1r = wrnd + 262144;   // 262144
    float* mlp_w2r = wrnd + 524288;   // 262144

    // 0. pre-round weights to tf32 (RN)
    k_round<<<192, 256>>>(qkv_w,  qkv_wr,  196608);
    k_round<<<64,  256>>>(proj_w, proj_wr, 65536);
    k_round<<<256, 256>>>(mlp_w1, mlp_w1r, 262144);
    k_round<<<256, 256>>>(mlp_w2, mlp_w2r, 262144);

    dim3 b328(32, 8);
    dim3 gtr(WW_/32, HH, BATCH*8);

    // 1. window partition
    k_winpart<<<gtr, b328>>>(x, wins);
    // 2. LN1 (tf32-rounded out)
    k_ln<<<NTOK/8, b328>>>(wins, n1_g, n1_b, hbuf);
    // 3. QKV GEMM -> big (stride 768)
    k_mma_gemm<<<dim3(NTOK/128, 768/128), 128>>>(hbuf, qkv_wr, qkv_b, nullptr, big, 768, 256, 0);
    // 4. attention -> hbuf (tf32-rounded out)
    k_attn<<<dim3(NWIN, NH), 64>>>(big, rel_b, hbuf);
    // 5. proj + residual(wins) -> wins (y)
    k_mma_gemm<<<dim3(NTOK/128, 256/128), 128>>>(hbuf, proj_wr, proj_b, wins, wins, 256, 256, 0);
    // 6-7. SE pooled gate
    k_pool_partial<<<576, 256>>>(wins, part);
    k_pool_gate<<<BATCH, 256>>>(part, se_w1, se_b1, se_w2, se_b2, gate);
    // 8. xf = y*gate (in place), hm = LN3(xf) -> hbuf (rounded)
    k_gate_ln<<<NTOK/8, b328>>>(wins, gate, n3_g, n3_b, hbuf);
    // 9. MLP1 + GELU -> big (stride 1024, rounded)
    k_mma_gemm<<<dim3(NTOK/128, 1024/128), 128>>>(hbuf, mlp_w1r, mlp_b1, nullptr, big, 1024, 256, 1);
    // 10. MLP2 + residual(xf) -> hbuf (final tokens)
    k_mma_gemm<<<dim3(NTOK/128, 256/128), 128>>>(big, mlp_w2r, mlp_b2, wins, hbuf, 256, 1024, 0);
    // 11. window reverse -> out
    k_winrev<<<gtr, b328>>>(hbuf, out);
}

// round 6
// speedup vs baseline: 2.8561x; 1.1784x over previous
#include <cuda_runtime.h>
#include <cuda_bf16.h>
#include <cstdint>
#include <math.h>

// ---------------------------------------------------------------------------
// HATBlock — Round 6: bf16 mma.sync (m16n8k16) GEMMs, LN/gate fused into GEMM
// A-loads, bf16 intermediates, pool fused into proj epilogue.
// B=4, C=256, H=W=192, WS=8, NH=8, HD=32
// ---------------------------------------------------------------------------

#define BATCH 4
#define DIM   256
#define HH    192
#define WW_   192
#define NWH   24
#define NWIN  (BATCH*NWH*NWH)   // 2304
#define NTOK  (NWIN*64)         // 147456
#define NH    8
#define TOK_PER_B (HH*WW_)      // 36864

typedef unsigned long long u64;
typedef unsigned int u32;

// -------------------- scratch (device globals; no runtime alloc) -----------
__device__ float g_wins[(size_t)NTOK*256];     // wins / y (fp32)
__device__ float g_h   [(size_t)NTOK*256];     // attn-out bf16 alias / final fp32
__device__ float g_big [(size_t)NTOK*512];     // qkv(768) / hidden(1024) as bf16
__device__ float g_part[1024];                 // pooled sums [B,256]
__device__ float g_gate[BATCH*256];
__device__ float g_wb  [786432/2];             // bf16 weights, transposed [N,K]

__device__ __forceinline__ float gelu_exact(float x) {
    return 0.5f * x * (1.0f + erff(x * 0.70710678118654752f));
}

__device__ __forceinline__ void cp_async16(void* smem, const void* gmem) {
    unsigned s = (unsigned)__cvta_generic_to_shared(smem);
    asm volatile("cp.async.ca.shared.global [%0], [%1], 16;" :: "r"(s), "l"(gmem));
}
__device__ __forceinline__ void cp_commit() { asm volatile("cp.async.commit_group;"); }
__device__ __forceinline__ void cp_wait0()  { asm volatile("cp.async.wait_group 0;" ::: "memory"); }
__device__ __forceinline__ void cp_wait2()  { asm volatile("cp.async.wait_group 2;" ::: "memory"); }

__device__ __forceinline__ void mma_bf16(float* c, const u32* a, const u32* b) {
    asm volatile(
        "mma.sync.aligned.m16n8k16.row.col.f32.bf16.bf16.f32 "
        "{%0,%1,%2,%3},{%4,%5,%6,%7},{%8,%9},{%0,%1,%2,%3};"
        : "+f"(c[0]), "+f"(c[1]), "+f"(c[2]), "+f"(c[3])
        : "r"(a[0]), "r"(a[1]), "r"(a[2]), "r"(a[3]), "r"(b[0]), "r"(b[1]));
}

// packed fp32x2 helpers (attention)
__device__ __forceinline__ u64 pk2(float a, float b) {
    u64 r; asm("mov.b64 %0, {%1,%2};" : "=l"(r) : "f"(a), "f"(b)); return r;
}
__device__ __forceinline__ void upk2(u64 v, float& a, float& b) {
    asm("mov.b64 {%0,%1}, %2;" : "=f"(a), "=f"(b) : "l"(v));
}
__device__ __forceinline__ u64 fma2(u64 a, u64 b, u64 c) {
    u64 d; asm("fma.rn.f32x2 %0, %1, %2, %3;" : "=l"(d) : "l"(a), "l"(b), "l"(c)); return d;
}
__device__ __forceinline__ u64 mul2(u64 a, u64 b) {
    u64 d; asm("mul.rn.f32x2 %0, %1, %2;" : "=l"(d) : "l"(a), "l"(b)); return d;
}

// -------------------- weight prep: fp32 [K,N] -> bf16 [N,K] ----------------
__global__ void k_wprep(const float* __restrict__ in, __nv_bfloat16* __restrict__ out,
                        int K, int N) {
    __shared__ float tile[32][33];
    int n0 = blockIdx.x * 32, k0 = blockIdx.y * 32;
    for (int r = threadIdx.y; r < 32; r += 8)
        tile[r][threadIdx.x] = in[(size_t)(k0 + r) * N + n0 + threadIdx.x];
    __syncthreads();
    for (int r = threadIdx.y; r < 32; r += 8)
        out[(size_t)(n0 + r) * K + k0 + threadIdx.x] = __float2bfloat16_rn(tile[threadIdx.x][r]);
}

// -------------------- window partition: x[B,C,H,W] -> wins[t,c] ------------
__global__ void k_winpart(const float* __restrict__ x, float* __restrict__ wins) {
    int w0 = blockIdx.x * 32, hh = blockIdx.y;
    int b = blockIdx.z >> 3, c0 = (blockIdx.z & 7) * 32;
    __shared__ float tile[32][33];
    for (int cc = threadIdx.y; cc < 32; cc += 8)
        tile[cc][threadIdx.x] =
            x[(((size_t)b*256 + c0 + cc)*HH + hh)*WW_ + w0 + threadIdx.x];
    __syncthreads();
    int hw = hh >> 3, i = hh & 7;
    for (int wi = threadIdx.y; wi < 32; wi += 8) {
        int w = w0 + wi, ww = w >> 3, j = w & 7;
        size_t t = (((size_t)b*NWH + hw)*NWH + ww)*64 + i*8 + j;
        wins[t*256 + c0 + threadIdx.x] = tile[threadIdx.x][wi];
    }
}

// -------------------- window reverse: z[t,c] -> out[B,C,H,W] ---------------
__global__ void k_winrev(const float* __restrict__ z, float* __restrict__ out) {
    int w0 = blockIdx.x * 32, hh = blockIdx.y;
    int b = blockIdx.z >> 3, c0 = (blockIdx.z & 7) * 32;
    __shared__ float tile[32][33];
    int hw = hh >> 3, i = hh & 7;
    for (int wi = threadIdx.y; wi < 32; wi += 8) {
        int w = w0 + wi, ww = w >> 3, j = w & 7;
        size_t t = (((size_t)b*NWH + hw)*NWH + ww)*64 + i*8 + j;
        tile[wi][threadIdx.x] = z[t*256 + c0 + threadIdx.x];
    }
    __syncthreads();
    for (int cc = threadIdx.y; cc < 32; cc += 8)
        out[(((size_t)b*256 + c0 + cc)*HH + hh)*WW_ + w0 + threadIdx.x] =
            tile[threadIdx.x][cc];
}

// ============================================================================
// GEMM 1: A cached in smem (optionally fp32 + gate + LN -> bf16), N-loop.
// C = epi(A[128,256] @ Wt[N,256]^T + bias).  Wt bf16 [N,K] row-major.
// 256 threads = 8 warps (4 m x 2 n), warp tile 32x64, K chunk 32, 4-stage B.
// smem: Ab bf16[128][264] @0 (67,584B); region2 @67,584:
//       fp32 staging [128][260] (133,120B, LN mode only, dead after LN)
//       B ring 4 x bf16[128][40] (40,960B)
//       scol[128] fp32 @108,544 (proj pool only)
// ============================================================================
#define AB_STR 264
#define SF_STR 260
#define B_STR  40
#define SMA_R2 67584
#define SMA_SCOL 108544
#define SMA_SMEM_LN   200704
#define SMA_SMEM_PROJ 109056

__global__ void __launch_bounds__(256, 2)
k_gemm_smA(const void* __restrict__ Ain, int a_bf16,
           const float* __restrict__ lng, const float* __restrict__ lnb,
           const float* __restrict__ gate,
           const __nv_bfloat16* __restrict__ Wt,
           const float* __restrict__ bias,
           const float* __restrict__ R,
           void* __restrict__ Cout, int c_bf16, int act,
           int Nfull, float* __restrict__ pool)
{
    extern __shared__ char smem[];
    __nv_bfloat16* Ab = (__nv_bfloat16*)smem;
    float* Sf   = (float*)(smem + SMA_R2);
    char*  Bring = smem + SMA_R2;
    float* scol = (float*)(smem + SMA_SCOL);

    const int tid = threadIdx.x, lane = tid & 31, wid = tid >> 5;
    const int g = lane >> 2, tig = lane & 3;
    const int arow = (wid & 3) * 32;     // warp m offset
    const int bcol = (wid >> 2) * 64;    // warp n offset (within 128)
    const int m0 = blockIdx.x * 128;
    const int b  = m0 / TOK_PER_B;

    // ---- load A ----
    if (a_bf16) {
        const __nv_bfloat16* Ag = (const __nv_bfloat16*)Ain + (size_t)m0 * 256;
#pragma unroll
        for (int i = 0; i < 16; i++) {
            int idx = tid + 256*i;            // 0..4095
            int r = idx >> 5, c8 = idx & 31;
            cp_async16(Ab + r*AB_STR + c8*8, Ag + (size_t)r*256 + c8*8);
        }
        cp_commit();
    } else {
        const float* Ag = (const float*)Ain + (size_t)m0 * 256;
#pragma unroll
        for (int i = 0; i < 32; i++) {
            int idx = tid + 256*i;            // 0..8191
            int r = idx >> 6, c4 = idx & 63;
            cp_async16(Sf + r*SF_STR + c4*4, Ag + (size_t)r*256 + c4*4);
        }
        cp_commit();
        cp_wait0();
        __syncthreads();
        // gate + LayerNorm, rows wid*16 .. wid*16+15
        const float* gp = gate ? (gate + b*256) : nullptr;
#pragma unroll 1
        for (int i = 0; i < 16; i++) {
            int r = wid*16 + i;
            float v[8], s = 0.f, s2 = 0.f;
#pragma unroll
            for (int j = 0; j < 8; j++) {
                int c = lane + 32*j;
                float t = Sf[r*SF_STR + c];
                if (gp) t *= gp[c];
                v[j] = t; s += t; s2 += t*t;
            }
#pragma unroll
            for (int o = 16; o; o >>= 1) {
                s  += __shfl_xor_sync(0xffffffffu, s,  o);
                s2 += __shfl_xor_sync(0xffffffffu, s2, o);
            }
            float mean = s * (1.f/256.f);
            float var  = s2 * (1.f/256.f) - mean*mean;
            float inv  = rsqrtf(var + 1e-5f);
#pragma unroll
            for (int j = 0; j < 8; j++) {
                int c = lane + 32*j;
                Ab[r*AB_STR + c] = __float2bfloat16_rn((v[j]-mean)*inv*lng[c] + lnb[c]);
            }
        }
        __syncthreads();
    }

    const int NY = Nfull >> 7;       // N / 128
    const int KT = 8;                // 256 / 32
    const int TOT = NY * KT;

    // B chunk filler: chunk c -> ny=c/8, kt=c&7, stage c&3
    auto fillB = [&](int c) {
        int ny2 = c >> 3, kt2 = c & 7, st = c & 3;
        __nv_bfloat16* Bs = (__nv_bfloat16*)(Bring + st*10240);
        const __nv_bfloat16* Wg = Wt + (size_t)(ny2*128) * 256 + kt2*32;
#pragma unroll
        for (int i = 0; i < 2; i++) {
            int idx = tid + 256*i;            // 0..511
            int row = idx >> 2, seg = idx & 3;
            cp_async16(Bs + row*B_STR + seg*8, Wg + (size_t)row*256 + seg*8);
        }
        cp_commit();
    };
    fillB(0); fillB(1); fillB(2);

    int ci = 0;
    for (int ny = 0; ny < NY; ny++) {
        float acc[2][8][4];
#pragma unroll
        for (int i = 0; i < 2; i++)
#pragma unroll
            for (int j = 0; j < 8; j++)
#pragma unroll
                for (int q = 0; q < 4; q++) acc[i][j][q] = 0.f;

        for (int kt = 0; kt < KT; kt++, ci++) {
            cp_wait2();
            __syncthreads();
            const __nv_bfloat16* Bs = (const __nv_bfloat16*)(Bring + (ci & 3)*10240);
#pragma unroll
            for (int ks = 0; ks < 2; ks++) {
                const int kb = kt*32 + ks*16 + 2*tig;
                u32 af[2][4], bf[8][2];
#pragma unroll
                for (int mt = 0; mt < 2; mt++) {
                    int r = arow + mt*16 + g;
                    af[mt][0] = *(const u32*)&Ab[(r   )*AB_STR + kb];
                    af[mt][1] = *(const u32*)&Ab[(r+8 )*AB_STR + kb];
                    af[mt][2] = *(const u32*)&Ab[(r   )*AB_STR + kb + 8];
                    af[mt][3] = *(const u32*)&Ab[(r+8 )*AB_STR + kb + 8];
                }
                const int kl = ks*16 + 2*tig;
#pragma unroll
                for (int nt = 0; nt < 8; nt++) {
                    int col = bcol + nt*8 + g;
                    bf[nt][0] = *(const u32*)&Bs[col*B_STR + kl];
                    bf[nt][1] = *(const u32*)&Bs[col*B_STR + kl + 8];
                }
#pragma unroll
                for (int mt = 0; mt < 2; mt++)
#pragma unroll
                    for (int nt = 0; nt < 8; nt++)
                        mma_bf16(acc[mt][nt], af[mt], bf[nt]);
            }
            if (ci + 3 < TOT) fillB(ci + 3);
            else cp_commit();
        }

        // ---- epilogue for this ny ----
        const int ncol0 = ny * 128;
        if (c_bf16) {
            __nv_bfloat16* Cb = (__nv_bfloat16*)Cout;
#pragma unroll
            for (int nt = 0; nt < 8; nt++) {
                int colG = ncol0 + bcol + nt*8 + 2*tig;
                float b0 = bias[colG], b1 = bias[colG + 1];
#pragma unroll
                for (int mt = 0; mt < 2; mt++) {
                    size_t r0 = (size_t)m0 + arow + mt*16 + g;
                    size_t r1 = r0 + 8;
                    float v00 = acc[mt][nt][0] + b0, v01 = acc[mt][nt][1] + b1;
                    float v10 = acc[mt][nt][2] + b0, v11 = acc[mt][nt][3] + b1;
                    if (act) {
                        v00 = gelu_exact(v00); v01 = gelu_exact(v01);
                        v10 = gelu_exact(v10); v11 = gelu_exact(v11);
                    }
                    *(__nv_bfloat162*)(Cb + r0*Nfull + colG) = __float22bfloat162_rn(make_float2(v00, v01));
                    *(__nv_bfloat162*)(Cb + r1*Nfull + colG) = __float22bfloat162_rn(make_float2(v10, v11));
                }
            }
        } else {
            float* Cf = (float*)Cout;
            float psum[8][2];
#pragma unroll
            for (int nt = 0; nt < 8; nt++) { psum[nt][0] = 0.f; psum[nt][1] = 0.f; }
#pragma unroll
            for (int nt = 0; nt < 8; nt++) {
                int colG = ncol0 + bcol + nt*8 + 2*tig;
                float b0 = bias[colG], b1 = bias[colG + 1];
#pragma unroll
                for (int mt = 0; mt < 2; mt++) {
                    size_t r0 = (size_t)m0 + arow + mt*16 + g;
                    size_t r1 = r0 + 8;
                    float2 q0 = *(const float2*)(R + r0*Nfull + colG);
                    float2 q1 = *(const float2*)(R + r1*Nfull + colG);
                    float v00 = acc[mt][nt][0] + b0 + q0.x, v01 = acc[mt][nt][1] + b1 + q0.y;
                    float v10 = acc[mt][nt][2] + b0 + q1.x, v11 = acc[mt][nt][3] + b1 + q1.y;
                    *(float2*)(Cf + r0*Nfull + colG) = make_float2(v00, v01);
                    *(float2*)(Cf + r1*Nfull + colG) = make_float2(v10, v11);
                    psum[nt][0] += v00 + v10; psum[nt][1] += v01 + v11;
                }
            }
            if (pool) {
                __syncthreads();
                if (tid < 128) scol[tid] = 0.f;
                __syncthreads();
#pragma unroll
                for (int nt = 0; nt < 8; nt++) {
                    int colL = bcol + nt*8 + 2*tig;
                    atomicAdd(&scol[colL],     psum[nt][0]);
                    atomicAdd(&scol[colL + 1], psum[nt][1]);
                }
                __syncthreads();
                if (tid < 128) atomicAdd(pool + b*256 + ncol0 + tid, scol[tid]);
                __syncthreads();
            }
        }
    }
}

// ============================================================================
// GEMM 2 (MLP2): A bf16 streamed [M,1024], Wt bf16 [256,1024], N-loop (2).
// out fp32 = acc + bias + R*gate.  4-stage A+B ring (one group per chunk).
// smem: As ring 4 x [128][40] @0; Bs ring 4 x [128][40] @40,960. (81,920B)
// ============================================================================
#define SA_SMEM 81920
__global__ void __launch_bounds__(256, 2)
k_gemm_sA(const __nv_bfloat16* __restrict__ Ain,
          const __nv_bfloat16* __restrict__ Wt,
          const float* __restrict__ bias,
          const float* __restrict__ R,
          const float* __restrict__ gate,
          float* __restrict__ Cout)
{
    extern __shared__ char smem[];
    const int tid = threadIdx.x, lane = tid & 31, wid = tid >> 5;
    const int g = lane >> 2, tig = lane & 3;
    const int arow = (wid & 3) * 32;
    const int bcol = (wid >> 2) * 64;
    const int m0 = blockIdx.x * 128;
    const int b  = m0 / TOK_PER_B;
    const int KT = 32, NY = 2, TOT = 64;

    const __nv_bfloat16* Ag = Ain + (size_t)m0 * 1024;

    auto fillC = [&](int c) {
        int ny2 = c >> 5, kt2 = c & 31, st = c & 3;
        __nv_bfloat16* As = (__nv_bfloat16*)(smem + st*10240);
        __nv_bfloat16* Bs = (__nv_bfloat16*)(smem + 40960 + st*10240);
        const __nv_bfloat16* Wg = Wt + (size_t)(ny2*128) * 1024 + kt2*32;
        const __nv_bfloat16* Ac = Ag + kt2*32;
#pragma unroll
        for (int i = 0; i < 2; i++) {
            int idx = tid + 256*i;
            int row = idx >> 2, seg = idx & 3;
            cp_async16(As + row*B_STR + seg*8, Ac + (size_t)row*1024 + seg*8);
            cp_async16(Bs + row*B_STR + seg*8, Wg + (size_t)row*1024 + seg*8);
        }
        cp_commit();
    };
    fillC(0); fillC(1); fillC(2);

    int ci = 0;
    for (int ny = 0; ny < NY; ny++) {
        float acc[2][8][4];
#pragma unroll
        for (int i = 0; i < 2; i++)
#pragma unroll
            for (int j = 0; j < 8; j++)
#pragma unroll
                for (int q = 0; q < 4; q++) acc[i][j][q] = 0.f;

        for (int kt = 0; kt < KT; kt++, ci++) {
            cp_wait2();
            __syncthreads();
            int st = ci & 3;
            const __nv_bfloat16* As = (const __nv_bfloat16*)(smem + st*10240);
            const __nv_bfloat16* Bs = (const __nv_bfloat16*)(smem + 40960 + st*10240);
#pragma unroll
            for (int ks = 0; ks < 2; ks++) {
                const int kl = ks*16 + 2*tig;
                u32 af[2][4], bf[8][2];
#pragma unroll
                for (int mt = 0; mt < 2; mt++) {
                    int r = arow + mt*16 + g;
                    af[mt][0] = *(const u32*)&As[(r   )*B_STR + kl];
                    af[mt][1] = *(const u32*)&As[(r+8 )*B_STR + kl];
                    af[mt][2] = *(const u32*)&As[(r   )*B_STR + kl + 8];
                    af[mt][3] = *(const u32*)&As[(r+8 )*B_STR + kl + 8];
                }
#pragma unroll
                for (int nt = 0; nt < 8; nt++) {
                    int col = bcol + nt*8 + g;
                    bf[nt][0] = *(const u32*)&Bs[col*B_STR + kl];
                    bf[nt][1] = *(const u32*)&Bs[col*B_STR + kl + 8];
                }
#pragma unroll
                for (int mt = 0; mt < 2; mt++)
#pragma unroll
                    for (int nt = 0; nt < 8; nt++)
                        mma_bf16(acc[mt][nt], af[mt], bf[nt]);
            }
            if (ci + 3 < TOT) fillC(ci + 3);
            else cp_commit();
        }

        const int ncol0 = ny * 128;
#pragma unroll
        for (int nt = 0; nt < 8; nt++) {
            int colG = ncol0 + bcol + nt*8 + 2*tig;
            float b0 = bias[colG], b1 = bias[colG + 1];
            float g0 = gate[b*256 + colG], g1 = gate[b*256 + colG + 1];
#pragma unroll
            for (int mt = 0; mt < 2; mt++) {
                size_t r0 = (size_t)m0 + arow + mt*16 + g;
                size_t r1 = r0 + 8;
                float2 q0 = *(const float2*)(R + r0*256 + colG);
                float2 q1 = *(const float2*)(R + r1*256 + colG);
                float v00 = acc[mt][nt][0] + b0 + q0.x*g0, v01 = acc[mt][nt][1] + b1 + q0.y*g1;
                float v10 = acc[mt][nt][2] + b0 + q1.x*g0, v11 = acc[mt][nt][3] + b1 + q1.y*g1;
                *(float2*)(Cout + r0*256 + colG) = make_float2(v00, v01);
                *(float2*)(Cout + r1*256 + colG) = make_float2(v10, v11);
            }
        }
    }
}

// -------------------- window attention (bf16 in/out, f32x2 math) -----------
__device__ __forceinline__ void bf8_to_f32(uint4 u, float* f) {
    float2 t;
    t = __bfloat1622float2(*(__nv_bfloat162*)&u.x); f[0]=t.x; f[1]=t.y;
    t = __bfloat1622float2(*(__nv_bfloat162*)&u.y); f[2]=t.x; f[3]=t.y;
    t = __bfloat1622float2(*(__nv_bfloat162*)&u.z); f[4]=t.x; f[5]=t.y;
    t = __bfloat1622float2(*(__nv_bfloat162*)&u.w); f[6]=t.x; f[7]=t.y;
}

__global__ void __launch_bounds__(64, 8) k_attn(const __nv_bfloat16* __restrict__ qkv,
                                                const float* __restrict__ rel_bias,
                                                __nv_bfloat16* __restrict__ o) {
    int win = blockIdx.x, h = blockIdx.y;
    int n = threadIdx.x;
    __shared__ __align__(16) float sk[64][32];
    __shared__ __align__(16) float sv[64][32];
    __shared__ float sb[225];

    size_t base = ((size_t)win*64 + n)*768 + h*32;
    const uint4* qp = (const uint4*)(qkv + base);
    const uint4* kp = (const uint4*)(qkv + base + 256);
    const uint4* vp = (const uint4*)(qkv + base + 512);
    u64 qr2[16];
#pragma unroll
    for (int c = 0; c < 4; c++) {
        float qf[8], kf[8], vf[8];
        bf8_to_f32(qp[c], qf); bf8_to_f32(kp[c], kf); bf8_to_f32(vp[c], vf);
#pragma unroll
        for (int j = 0; j < 4; j++) qr2[c*4 + j] = pk2(qf[2*j], qf[2*j+1]);
#pragma unroll
        for (int j = 0; j < 8; j++) { sk[n][c*8+j] = kf[j]; sv[n][c*8+j] = vf[j]; }
    }
    for (int r = n; r < 225; r += 64) sb[r] = rel_bias[r*NH + h];
    __syncthreads();

    const int i1 = n >> 3, j1 = n & 7;
    u64 acc2[16];
#pragma unroll
    for (int q = 0; q < 16; q++) acc2[q] = 0ull;
    float mx = -1e30f, sum = 0.f;
    float s[32];

#pragma unroll
    for (int chunk = 0; chunk < 2; chunk++) {
        const int mbase = chunk * 32;
#pragma unroll 4
        for (int mm = 0; mm < 32; mm++) {
            int m = mbase + mm;
            const float4* kr = (const float4*)sk[m];
            u64 da = 0ull, db = 0ull;
#pragma unroll
            for (int q8 = 0; q8 < 8; q8++) {
                float4 kv = kr[q8];
                da = fma2(qr2[2*q8],   pk2(kv.x, kv.y), da);
                db = fma2(qr2[2*q8+1], pk2(kv.z, kv.w), db);
            }
            float a, bq, c, d;
            upk2(da, a, bq); upk2(db, c, d);
            int i2 = m >> 3, j2 = m & 7;
            s[mm] = (a+bq+c+d) * 0.17677669529663687f + sb[(i1-i2+7)*15 + (j1-j2+7)];
        }
        float cmx = -1e30f;
#pragma unroll
        for (int mm = 0; mm < 32; mm++) cmx = fmaxf(cmx, s[mm]);
        float M = fmaxf(mx, cmx);
        float f = __expf(mx - M);
        sum *= f;
        u64 f2 = pk2(f, f);
#pragma unroll
        for (int q = 0; q < 16; q++) acc2[q] = mul2(acc2[q], f2);
#pragma unroll 4
        for (int mm = 0; mm < 32; mm++) {
            int m = mbase + mm;
            float p = __expf(s[mm] - M);
            sum += p;
            u64 p2 = pk2(p, p);
            const float4* vr = (const float4*)sv[m];
#pragma unroll
            for (int q8 = 0; q8 < 8; q8++) {
                float4 vv = vr[q8];
                acc2[2*q8]   = fma2(p2, pk2(vv.x, vv.y), acc2[2*q8]);
                acc2[2*q8+1] = fma2(p2, pk2(vv.z, vv.w), acc2[2*q8+1]);
            }
        }
        mx = M;
    }

    float inv = 1.f / sum;
    __nv_bfloat16* op = o + ((size_t)win*64 + n)*256 + h*32;
#pragma unroll
    for (int c = 0; c < 4; c++) {
        uint4 u;
        float a0,b0,a1,b1,a2,b2,a3,b3;
        upk2(acc2[c*4+0], a0, b0); upk2(acc2[c*4+1], a1, b1);
        upk2(acc2[c*4+2], a2, b2); upk2(acc2[c*4+3], a3, b3);
        *(__nv_bfloat162*)&u.x = __float22bfloat162_rn(make_float2(a0*inv, b0*inv));
        *(__nv_bfloat162*)&u.y = __float22bfloat162_rn(make_float2(a1*inv, b1*inv));
        *(__nv_bfloat162*)&u.z = __float22bfloat162_rn(make_float2(a2*inv, b2*inv));
        *(__nv_bfloat162*)&u.w = __float22bfloat162_rn(make_float2(a3*inv, b3*inv));
        *(uint4*)(op + c*8) = u;
    }
}

// -------------------- SE gate from completed pooled sums --------------------
__global__ void __launch_bounds__(256) k_pool_gate(const float* __restrict__ part,
                                                   const float* __restrict__ w1,
                                                   const float* __restrict__ b1,
                                                   const float* __restrict__ w2,
                                                   const float* __restrict__ b2,
                                                   float* __restrict__ gate) {
    int b = blockIdx.x;
    float pooled = part[b*256 + threadIdx.x] * (1.f / (float)TOK_PER_B);
    __shared__ float sp[256];
    __shared__ float hid[16];
    sp[threadIdx.x] = pooled;
    __syncthreads();
    if (threadIdx.x < 16) {
        float a = b1[threadIdx.x];
        for (int c = 0; c < 256; c++) a = fmaf(sp[c], w1[c*16 + threadIdx.x], a);
        hid[threadIdx.x] = fmaxf(a, 0.f);
    }
    __syncthreads();
    float g = b2[threadIdx.x];
#pragma unroll
    for (int j = 0; j < 16; j++) g = fmaf(hid[j], w2[j*256 + threadIdx.x], g);
    gate[b*256 + threadIdx.x] = 1.f / (1.f + __expf(-g));
}

// ---------------------------------------------------------------------------
extern "C" void kernel_launch(void* const* d_in, const int* in_sizes, int n_in,
                              void* d_out, int out_size) {
    const float* x      = (const float*)d_in[0];
    const float* n1_g   = (const float*)d_in[1];
    const float* n1_b   = (const float*)d_in[2];
    const float* qkv_w  = (const float*)d_in[3];
    const float* qkv_b  = (const float*)d_in[4];
    const float* proj_w = (const float*)d_in[5];
    const float* proj_b = (const float*)d_in[6];
    const float* rel_b  = (const float*)d_in[7];
    const float* se_w1  = (const float*)d_in[8];
    const float* se_b1  = (const float*)d_in[9];
    const float* se_w2  = (const float*)d_in[10];
    const float* se_b2  = (const float*)d_in[11];
    const float* n3_g   = (const float*)d_in[12];
    const float* n3_b   = (const float*)d_in[13];
    const float* mlp_w1 = (const float*)d_in[14];
    const float* mlp_b1 = (const float*)d_in[15];
    const float* mlp_w2 = (const float*)d_in[16];
    const float* mlp_b2 = (const float*)d_in[17];
    float* out = (float*)d_out;

    float *wins, *hbuf, *big, *part, *gate, *wb;
    cudaGetSymbolAddress((void**)&wins, g_wins);
    cudaGetSymbolAddress((void**)&hbuf, g_h);
    cudaGetSymbolAddress((void**)&big,  g_big);
    cudaGetSymbolAddress((void**)&part, g_part);
    cudaGetSymbolAddress((void**)&gate, g_gate);
    cudaGetSymbolAddress((void**)&wb,   g_wb);

    __nv_bfloat16* wbf   = (__nv_bfloat16*)wb;
    __nv_bfloat16* qkvW  = wbf;            // [768,256]
    __nv_bfloat16* projW = wbf + 196608;   // [256,256]
    __nv_bfloat16* w1W   = wbf + 262144;   // [1024,256]
    __nv_bfloat16* w2W   = wbf + 524288;   // [256,1024]
    __nv_bfloat16* bigb  = (__nv_bfloat16*)big;
    __nv_bfloat16* hb    = (__nv_bfloat16*)hbuf;

    cudaFuncSetAttribute(k_gemm_smA, cudaFuncAttributeMaxDynamicSharedMemorySize, SMA_SMEM_LN);
    cudaFuncSetAttribute(k_gemm_sA,  cudaFuncAttributeMaxDynamicSharedMemorySize, SA_SMEM);

    dim3 b328(32, 8);

    // 0. zero pooled sums; prep bf16 transposed weights
    cudaMemsetAsync(part, 0, 1024 * sizeof(float));
    k_wprep<<<dim3(24, 8),  b328>>>(qkv_w,  qkvW,  256, 768);
    k_wprep<<<dim3(8,  8),  b328>>>(proj_w, projW, 256, 256);
    k_wprep<<<dim3(32, 8),  b328>>>(mlp_w1, w1W,   256, 1024);
    k_wprep<<<dim3(8,  32), b328>>>(mlp_w2, w2W,   1024, 256);

    dim3 gtr(WW_/32, HH, BATCH*8);
    // 1. window partition
    k_winpart<<<gtr, b328>>>(x, wins);
    // 2. QKV (LN1 fused) -> big bf16 [NTOK,768]
    k_gemm_smA<<<NTOK/128, 256, SMA_SMEM_LN>>>(wins, 0, n1_g, n1_b, nullptr,
                                               qkvW, qkv_b, nullptr,
                                               bigb, 1, 0, 768, nullptr);
    // 3. attention -> hb bf16 [NTOK,256]
    k_attn<<<dim3(NWIN, NH), 64>>>(bigb, rel_b, hb);
    // 4. proj + residual(wins) -> wins fp32 (y), pooled sums -> part
    k_gemm_smA<<<NTOK/128, 256, SMA_SMEM_PROJ>>>(hb, 1, nullptr, nullptr, nullptr,
                                                 projW, proj_b, wins,
                                                 wins, 0, 0, 256, part);
    // 5. SE gate
    k_pool_gate<<<BATCH, 256>>>(part, se_w1, se_b1, se_w2, se_b2, gate);
    // 6. MLP1 (gate+LN3 fused) + GELU -> big bf16 [NTOK,1024]
    k_gemm_smA<<<NTOK/128, 256, SMA_SMEM_LN>>>(wins, 0, n3_g, n3_b, gate,
                                               w1W, mlp_b1, nullptr,
                                               bigb, 1, 1, 1024, nullptr);
    // 7. MLP2 + residual(y*gate) -> hbuf fp32
    k_gemm_sA<<<NTOK/128, 256, SA_SMEM>>>(bigb, w2W, mlp_b2, wins, gate, hbuf);
    // 8. window reverse -> out
    k_winrev<<<gtr, b328>>>(hbuf, out);
}

// round 7
// speedup vs baseline: 3.5206x; 1.2326x over previous
#include <cuda_runtime.h>
#include <cuda_bf16.h>
#include <cstdint>
#include <math.h>

// ---------------------------------------------------------------------------
// HATBlock — Round 7: tensor-core attention (warp per window-head),
// GEMM LN-mode via direct LDG (2 CTAs/SM), bf16 everywhere on tensor paths.
// B=4, C=256, H=W=192, WS=8, NH=8, HD=32
// ---------------------------------------------------------------------------

#define BATCH 4
#define DIM   256
#define HH    192
#define WW_   192
#define NWH   24
#define NWIN  (BATCH*NWH*NWH)   // 2304
#define NTOK  (NWIN*64)         // 147456
#define NH    8
#define TOK_PER_B (HH*WW_)      // 36864

typedef unsigned long long u64;
typedef unsigned int u32;

// -------------------- scratch (device globals; no runtime alloc) -----------
__device__ float g_wins[(size_t)NTOK*256];     // wins / y (fp32)
__device__ float g_h   [(size_t)NTOK*256];     // attn-out bf16 alias / final fp32
__device__ float g_big [(size_t)NTOK*512];     // qkv(768) / hidden(1024) as bf16
__device__ float g_part[1024];                 // pooled sums [B,256]
__device__ float g_gate[BATCH*256];
__device__ float g_wb  [786432/2];             // bf16 weights, transposed [N,K]

__device__ __forceinline__ float gelu_exact(float x) {
    return 0.5f * x * (1.0f + erff(x * 0.70710678118654752f));
}

__device__ __forceinline__ void cp_async16(void* smem, const void* gmem) {
    unsigned s = (unsigned)__cvta_generic_to_shared(smem);
    asm volatile("cp.async.ca.shared.global [%0], [%1], 16;" :: "r"(s), "l"(gmem));
}
__device__ __forceinline__ void cp_commit() { asm volatile("cp.async.commit_group;"); }
__device__ __forceinline__ void cp_wait2()  { asm volatile("cp.async.wait_group 2;" ::: "memory"); }

__device__ __forceinline__ void mma_bf16(float* c, const u32* a, const u32* b) {
    asm volatile(
        "mma.sync.aligned.m16n8k16.row.col.f32.bf16.bf16.f32 "
        "{%0,%1,%2,%3},{%4,%5,%6,%7},{%8,%9},{%0,%1,%2,%3};"
        : "+f"(c[0]), "+f"(c[1]), "+f"(c[2]), "+f"(c[3])
        : "r"(a[0]), "r"(a[1]), "r"(a[2]), "r"(a[3]), "r"(b[0]), "r"(b[1]));
}

__device__ __forceinline__ u32 packbf(float a, float b) {
    __nv_bfloat162 t = __float22bfloat162_rn(make_float2(a, b));
    return *(u32*)&t;
}

// -------------------- weight prep: fp32 [K,N] -> bf16 [N,K] ----------------
__global__ void k_wprep(const float* __restrict__ in, __nv_bfloat16* __restrict__ out,
                        int K, int N) {
    __shared__ float tile[32][33];
    int n0 = blockIdx.x * 32, k0 = blockIdx.y * 32;
    for (int r = threadIdx.y; r < 32; r += 8)
        tile[r][threadIdx.x] = in[(size_t)(k0 + r) * N + n0 + threadIdx.x];
    __syncthreads();
    for (int r = threadIdx.y; r < 32; r += 8)
        out[(size_t)(n0 + r) * K + k0 + threadIdx.x] = __float2bfloat16_rn(tile[threadIdx.x][r]);
}

// -------------------- window partition: x[B,C,H,W] -> wins[t,c] ------------
__global__ void k_winpart(const float* __restrict__ x, float* __restrict__ wins) {
    int w0 = blockIdx.x * 32, hh = blockIdx.y;
    int b = blockIdx.z >> 3, c0 = (blockIdx.z & 7) * 32;
    __shared__ float tile[32][33];
    for (int cc = threadIdx.y; cc < 32; cc += 8)
        tile[cc][threadIdx.x] =
            x[(((size_t)b*256 + c0 + cc)*HH + hh)*WW_ + w0 + threadIdx.x];
    __syncthreads();
    int hw = hh >> 3, i = hh & 7;
    for (int wi = threadIdx.y; wi < 32; wi += 8) {
        int w = w0 + wi, ww = w >> 3, j = w & 7;
        size_t t = (((size_t)b*NWH + hw)*NWH + ww)*64 + i*8 + j;
        wins[t*256 + c0 + threadIdx.x] = tile[threadIdx.x][wi];
    }
}

// -------------------- window reverse: z[t,c] -> out[B,C,H,W] ---------------
__global__ void k_winrev(const float* __restrict__ z, float* __restrict__ out) {
    int w0 = blockIdx.x * 32, hh = blockIdx.y;
    int b = blockIdx.z >> 3, c0 = (blockIdx.z & 7) * 32;
    __shared__ float tile[32][33];
    int hw = hh >> 3, i = hh & 7;
    for (int wi = threadIdx.y; wi < 32; wi += 8) {
        int w = w0 + wi, ww = w >> 3, j = w & 7;
        size_t t = (((size_t)b*NWH + hw)*NWH + ww)*64 + i*8 + j;
        tile[wi][threadIdx.x] = z[t*256 + c0 + threadIdx.x];
    }
    __syncthreads();
    for (int cc = threadIdx.y; cc < 32; cc += 8)
        out[(((size_t)b*256 + c0 + cc)*HH + hh)*WW_ + w0 + threadIdx.x] =
            tile[threadIdx.x][cc];
}

// ============================================================================
// GEMM 1: A cached in smem bf16 (optionally with fused gate+LN from fp32 gmem).
// C = epi(A[128,256] @ Wt[N,256]^T + bias).  Wt bf16 [N,K] row-major.
// 256 threads = 8 warps (4 m x 2 n), warp tile 32x64, K chunk 32, 4-stage B.
// smem: Ab bf16[128][264] @0 (67,584B); B ring 4x10,240 @67,584; scol @108,544.
// ============================================================================
#define AB_STR 264
#define B_STR  40
#define SMA_BR 67584
#define SMA_SCOL 108544
#define SMA_SMEM 109056

__global__ void __launch_bounds__(256, 2)
k_gemm_smA(const void* __restrict__ Ain, int a_bf16,
           const float* __restrict__ lng, const float* __restrict__ lnb,
           const float* __restrict__ gate,
           const __nv_bfloat16* __restrict__ Wt,
           const float* __restrict__ bias,
           const float* __restrict__ R,
           void* __restrict__ Cout, int c_bf16, int act,
           int Nfull, float* __restrict__ pool)
{
    extern __shared__ char smem[];
    __nv_bfloat16* Ab = (__nv_bfloat16*)smem;
    char*  Bring = smem + SMA_BR;
    float* scol = (float*)(smem + SMA_SCOL);

    const int tid = threadIdx.x, lane = tid & 31, wid = tid >> 5;
    const int g = lane >> 2, tig = lane & 3;
    const int arow = (wid & 3) * 32;
    const int bcol = (wid >> 2) * 64;
    const int m0 = blockIdx.x * 128;
    const int b  = m0 / TOK_PER_B;

    // ---- load A ----
    if (a_bf16) {
        const __nv_bfloat16* Ag = (const __nv_bfloat16*)Ain + (size_t)m0 * 256;
#pragma unroll
        for (int i = 0; i < 16; i++) {
            int idx = tid + 256*i;
            int r = idx >> 5, c8 = idx & 31;
            cp_async16(Ab + r*AB_STR + c8*8, Ag + (size_t)r*256 + c8*8);
        }
        cp_commit();
    } else {
        // fused (gate)+LN from fp32 gmem, direct LDG -> regs -> bf16 smem
        const float* Ag = (const float*)Ain + (size_t)m0 * 256;
        const float* gp = gate ? (gate + b*256) : nullptr;
        float gv[8], lg[8], lb[8];
#pragma unroll
        for (int j = 0; j < 8; j++) {
            int c = lane*8 + j;
            gv[j] = gp ? gp[c] : 1.f;
            lg[j] = lng[c]; lb[j] = lnb[c];
        }
#pragma unroll 1
        for (int i = 0; i < 16; i++) {
            int r = wid*16 + i;
            const float4* rp = (const float4*)(Ag + (size_t)r * 256 + lane*8);
            float4 va = rp[0], vb = rp[1];
            float v[8] = {va.x, va.y, va.z, va.w, vb.x, vb.y, vb.z, vb.w};
            float s = 0.f, s2 = 0.f;
#pragma unroll
            for (int j = 0; j < 8; j++) {
                v[j] *= gv[j]; s += v[j]; s2 += v[j]*v[j];
            }
#pragma unroll
            for (int o = 16; o; o >>= 1) {
                s  += __shfl_xor_sync(0xffffffffu, s,  o);
                s2 += __shfl_xor_sync(0xffffffffu, s2, o);
            }
            float mean = s * (1.f/256.f);
            float var  = s2 * (1.f/256.f) - mean*mean;
            float inv  = rsqrtf(var + 1e-5f);
#pragma unroll
            for (int k = 0; k < 4; k++) {
                float n0 = (v[2*k  ]-mean)*inv*lg[2*k  ] + lb[2*k  ];
                float n1 = (v[2*k+1]-mean)*inv*lg[2*k+1] + lb[2*k+1];
                *(u32*)&Ab[r*AB_STR + lane*8 + 2*k] = packbf(n0, n1);
            }
        }
        __syncthreads();
    }

    const int NY = Nfull >> 7;
    const int KT = 8;
    const int TOT = NY * KT;

    auto fillB = [&](int c) {
        int ny2 = c >> 3, kt2 = c & 7, st = c & 3;
        __nv_bfloat16* Bs = (__nv_bfloat16*)(Bring + st*10240);
        const __nv_bfloat16* Wg = Wt + (size_t)(ny2*128) * 256 + kt2*32;
#pragma unroll
        for (int i = 0; i < 2; i++) {
            int idx = tid + 256*i;
            int row = idx >> 2, seg = idx & 3;
            cp_async16(Bs + row*B_STR + seg*8, Wg + (size_t)row*256 + seg*8);
        }
        cp_commit();
    };
    fillB(0); fillB(1); fillB(2);

    int ci = 0;
    for (int ny = 0; ny < NY; ny++) {
        float acc[2][8][4];
#pragma unroll
        for (int i = 0; i < 2; i++)
#pragma unroll
            for (int j = 0; j < 8; j++)
#pragma unroll
                for (int q = 0; q < 4; q++) acc[i][j][q] = 0.f;

        for (int kt = 0; kt < KT; kt++, ci++) {
            cp_wait2();
            __syncthreads();
            const __nv_bfloat16* Bs = (const __nv_bfloat16*)(Bring + (ci & 3)*10240);
#pragma unroll
            for (int ks = 0; ks < 2; ks++) {
                const int kb = kt*32 + ks*16 + 2*tig;
                u32 af[2][4], bf[8][2];
#pragma unroll
                for (int mt = 0; mt < 2; mt++) {
                    int r = arow + mt*16 + g;
                    af[mt][0] = *(const u32*)&Ab[(r   )*AB_STR + kb];
                    af[mt][1] = *(const u32*)&Ab[(r+8 )*AB_STR + kb];
                    af[mt][2] = *(const u32*)&Ab[(r   )*AB_STR + kb + 8];
                    af[mt][3] = *(const u32*)&Ab[(r+8 )*AB_STR + kb + 8];
                }
                const int kl = ks*16 + 2*tig;
#pragma unroll
                for (int nt = 0; nt < 8; nt++) {
                    int col = bcol + nt*8 + g;
                    bf[nt][0] = *(const u32*)&Bs[col*B_STR + kl];
                    bf[nt][1] = *(const u32*)&Bs[col*B_STR + kl + 8];
                }
#pragma unroll
                for (int mt = 0; mt < 2; mt++)
#pragma unroll
                    for (int nt = 0; nt < 8; nt++)
                        mma_bf16(acc[mt][nt], af[mt], bf[nt]);
            }
            if (ci + 3 < TOT) fillB(ci + 3);
            else cp_commit();
        }

        const int ncol0 = ny * 128;
        if (c_bf16) {
            __nv_bfloat16* Cb = (__nv_bfloat16*)Cout;
#pragma unroll
            for (int nt = 0; nt < 8; nt++) {
                int colG = ncol0 + bcol + nt*8 + 2*tig;
                float b0 = bias[colG], b1 = bias[colG + 1];
#pragma unroll
                for (int mt = 0; mt < 2; mt++) {
                    size_t r0 = (size_t)m0 + arow + mt*16 + g;
                    size_t r1 = r0 + 8;
                    float v00 = acc[mt][nt][0] + b0, v01 = acc[mt][nt][1] + b1;
                    float v10 = acc[mt][nt][2] + b0, v11 = acc[mt][nt][3] + b1;
                    if (act) {
                        v00 = gelu_exact(v00); v01 = gelu_exact(v01);
                        v10 = gelu_exact(v10); v11 = gelu_exact(v11);
                    }
                    *(u32*)((__nv_bfloat16*)Cb + r0*Nfull + colG) = packbf(v00, v01);
                    *(u32*)((__nv_bfloat16*)Cb + r1*Nfull + colG) = packbf(v10, v11);
                }
            }
        } else {
            float* Cf = (float*)Cout;
            float psum[8][2];
#pragma unroll
            for (int nt = 0; nt < 8; nt++) { psum[nt][0] = 0.f; psum[nt][1] = 0.f; }
#pragma unroll
            for (int nt = 0; nt < 8; nt++) {
                int colG = ncol0 + bcol + nt*8 + 2*tig;
                float b0 = bias[colG], b1 = bias[colG + 1];
#pragma unroll
                for (int mt = 0; mt < 2; mt++) {
                    size_t r0 = (size_t)m0 + arow + mt*16 + g;
                    size_t r1 = r0 + 8;
                    float2 q0 = *(const float2*)(R + r0*Nfull + colG);
                    float2 q1 = *(const float2*)(R + r1*Nfull + colG);
                    float v00 = acc[mt][nt][0] + b0 + q0.x, v01 = acc[mt][nt][1] + b1 + q0.y;
                    float v10 = acc[mt][nt][2] + b0 + q1.x, v11 = acc[mt][nt][3] + b1 + q1.y;
                    *(float2*)(Cf + r0*Nfull + colG) = make_float2(v00, v01);
                    *(float2*)(Cf + r1*Nfull + colG) = make_float2(v10, v11);
                    psum[nt][0] += v00 + v10; psum[nt][1] += v01 + v11;
                }
            }
            if (pool) {
                __syncthreads();
                if (tid < 128) scol[tid] = 0.f;
                __syncthreads();
#pragma unroll
                for (int nt = 0; nt < 8; nt++) {
                    int colL = bcol + nt*8 + 2*tig;
                    atomicAdd(&scol[colL],     psum[nt][0]);
                    atomicAdd(&scol[colL + 1], psum[nt][1]);
                }
                __syncthreads();
                if (tid < 128) atomicAdd(pool + b*256 + ncol0 + tid, scol[tid]);
                __syncthreads();
            }
        }
    }
}

// ============================================================================
// GEMM 2 (MLP2): A bf16 streamed [M,1024], Wt bf16 [256,1024], N-loop (2).
// ============================================================================
#define SA_SMEM 81920
__global__ void __launch_bounds__(256, 2)
k_gemm_sA(const __nv_bfloat16* __restrict__ Ain,
          const __nv_bfloat16* __restrict__ Wt,
          const float* __restrict__ bias,
          const float* __restrict__ R,
          const float* __restrict__ gate,
          float* __restrict__ Cout)
{
    extern __shared__ char smem[];
    const int tid = threadIdx.x, lane = tid & 31, wid = tid >> 5;
    const int g = lane >> 2, tig = lane & 3;
    const int arow = (wid & 3) * 32;
    const int bcol = (wid >> 2) * 64;
    const int m0 = blockIdx.x * 128;
    const int b  = m0 / TOK_PER_B;
    const int KT = 32, NY = 2, TOT = 64;

    const __nv_bfloat16* Ag = Ain + (size_t)m0 * 1024;

    auto fillC = [&](int c) {
        int ny2 = c >> 5, kt2 = c & 31, st = c & 3;
        __nv_bfloat16* As = (__nv_bfloat16*)(smem + st*10240);
        __nv_bfloat16* Bs = (__nv_bfloat16*)(smem + 40960 + st*10240);
        const __nv_bfloat16* Wg = Wt + (size_t)(ny2*128) * 1024 + kt2*32;
        const __nv_bfloat16* Ac = Ag + kt2*32;
#pragma unroll
        for (int i = 0; i < 2; i++) {
            int idx = tid + 256*i;
            int row = idx >> 2, seg = idx & 3;
            cp_async16(As + row*B_STR + seg*8, Ac + (size_t)row*1024 + seg*8);
            cp_async16(Bs + row*B_STR + seg*8, Wg + (size_t)row*1024 + seg*8);
        }
        cp_commit();
    };
    fillC(0); fillC(1); fillC(2);

    int ci = 0;
    for (int ny = 0; ny < NY; ny++) {
        float acc[2][8][4];
#pragma unroll
        for (int i = 0; i < 2; i++)
#pragma unroll
            for (int j = 0; j < 8; j++)
#pragma unroll
                for (int q = 0; q < 4; q++) acc[i][j][q] = 0.f;

        for (int kt = 0; kt < KT; kt++, ci++) {
            cp_wait2();
            __syncthreads();
            int st = ci & 3;
            const __nv_bfloat16* As = (const __nv_bfloat16*)(smem + st*10240);
            const __nv_bfloat16* Bs = (const __nv_bfloat16*)(smem + 40960 + st*10240);
#pragma unroll
            for (int ks = 0; ks < 2; ks++) {
                const int kl = ks*16 + 2*tig;
                u32 af[2][4], bf[8][2];
#pragma unroll
                for (int mt = 0; mt < 2; mt++) {
                    int r = arow + mt*16 + g;
                    af[mt][0] = *(const u32*)&As[(r   )*B_STR + kl];
                    af[mt][1] = *(const u32*)&As[(r+8 )*B_STR + kl];
                    af[mt][2] = *(const u32*)&As[(r   )*B_STR + kl + 8];
                    af[mt][3] = *(const u32*)&As[(r+8 )*B_STR + kl + 8];
                }
#pragma unroll
                for (int nt = 0; nt < 8; nt++) {
                    int col = bcol + nt*8 + g;
                    bf[nt][0] = *(const u32*)&Bs[col*B_STR + kl];
                    bf[nt][1] = *(const u32*)&Bs[col*B_STR + kl + 8];
                }
#pragma unroll
                for (int mt = 0; mt < 2; mt++)
#pragma unroll
                    for (int nt = 0; nt < 8; nt++)
                        mma_bf16(acc[mt][nt], af[mt], bf[nt]);
            }
            if (ci + 3 < TOT) fillC(ci + 3);
            else cp_commit();
        }

        const int ncol0 = ny * 128;
#pragma unroll
        for (int nt = 0; nt < 8; nt++) {
            int colG = ncol0 + bcol + nt*8 + 2*tig;
            float b0 = bias[colG], b1 = bias[colG + 1];
            float g0 = gate[b*256 + colG], g1 = gate[b*256 + colG + 1];
#pragma unroll
            for (int mt = 0; mt < 2; mt++) {
                size_t r0 = (size_t)m0 + arow + mt*16 + g;
                size_t r1 = r0 + 8;
                float2 q0 = *(const float2*)(R + r0*256 + colG);
                float2 q1 = *(const float2*)(R + r1*256 + colG);
                float v00 = acc[mt][nt][0] + b0 + q0.x*g0, v01 = acc[mt][nt][1] + b1 + q0.y*g1;
                float v10 = acc[mt][nt][2] + b0 + q1.x*g0, v11 = acc[mt][nt][3] + b1 + q1.y*g1;
                *(float2*)(Cout + r0*256 + colG) = make_float2(v00, v01);
                *(float2*)(Cout + r1*256 + colG) = make_float2(v10, v11);
            }
        }
    }
}

// ============================================================================
// Tensor-core window attention: one warp per (window, head).
// S = Q K^T (m16n8k16, fp32 acc) + rel bias; 2-chunk online softmax;
// O = P V with P bf16 (S-frag -> A-frag register reuse); out bf16.
// Q/K fragments loaded directly from gmem; V transposed into per-warp smem.
// ============================================================================
__global__ void __launch_bounds__(128) k_attn_tc(const __nv_bfloat16* __restrict__ qkv,
                                                 const float* __restrict__ rel_bias,
                                                 __nv_bfloat16* __restrict__ o) {
    __shared__ __align__(16) __nv_bfloat16 VtAll[4][32][72];
    __shared__ float sbAll[4][226];

    const int lane = threadIdx.x & 31;
    const int wid  = threadIdx.x >> 5;
    const int g = lane >> 2, tig = lane & 3;
    const int win = blockIdx.x;
    const int h = blockIdx.y * 4 + wid;

    __nv_bfloat16 (*Vt)[72] = VtAll[wid];
    float* sb = sbAll[wid];

    const __nv_bfloat16* qw = qkv + (size_t)win * 64 * 768 + h * 32;        // Q base
    const __nv_bfloat16* kw = qw + 256;
    const __nv_bfloat16* vw = qw + 512;

    // bias gather for this head
    for (int r = lane; r < 225; r += 32) sb[r] = rel_bias[r*NH + h];

    // V transpose into smem: Vt[d][key]
#pragma unroll
    for (int i = 0; i < 32; i++) {
        int idx = lane + 32*i;          // 0..1023
        int n = idx >> 4, dp = idx & 15;
        u32 u = *(const u32*)(vw + (size_t)n*768 + 2*dp);
        __nv_bfloat162 v2 = *(__nv_bfloat162*)&u;
        Vt[2*dp  ][n] = v2.x;
        Vt[2*dp+1][n] = v2.y;
    }
    __syncwarp();

    float O[4][4][4];
#pragma unroll
    for (int a = 0; a < 4; a++)
#pragma unroll
        for (int bq = 0; bq < 4; bq++)
#pragma unroll
            for (int c = 0; c < 4; c++) O[a][bq][c] = 0.f;
    float mrow[8], lrow[8];
#pragma unroll
    for (int r = 0; r < 8; r++) { mrow[r] = -1e30f; lrow[r] = 0.f; }

#pragma unroll 1
    for (int ck = 0; ck < 2; ck++) {
        float S[4][4][4];
#pragma unroll
        for (int a = 0; a < 4; a++)
#pragma unroll
            for (int bq = 0; bq < 4; bq++)
#pragma unroll
                for (int c = 0; c < 4; c++) S[a][bq][c] = 0.f;

        // S = Q K^T for this 64x32 chunk
#pragma unroll
        for (int ks = 0; ks < 2; ks++) {
            const int kc = 16*ks + 2*tig;
            u32 aQ[4][4], bK[4][2];
#pragma unroll
            for (int mt = 0; mt < 4; mt++) {
                const __nv_bfloat16* q0 = qw + (size_t)(mt*16 + g)*768 + kc;
                aQ[mt][0] = *(const u32*)(q0);
                aQ[mt][1] = *(const u32*)(q0 + 8*768);
                aQ[mt][2] = *(const u32*)(q0 + 8);
                aQ[mt][3] = *(const u32*)(q0 + 8*768 + 8);
            }
#pragma unroll
            for (int nt = 0; nt < 4; nt++) {
                const __nv_bfloat16* k0 = kw + (size_t)(ck*32 + nt*8 + g)*768 + kc;
                bK[nt][0] = *(const u32*)(k0);
                bK[nt][1] = *(const u32*)(k0 + 8);
            }
#pragma unroll
            for (int mt = 0; mt < 4; mt++)
#pragma unroll
                for (int nt = 0; nt < 4; nt++)
                    mma_bf16(S[mt][nt], aQ[mt], bK[nt]);
        }

        // scale + relative bias
#pragma unroll
        for (int mt = 0; mt < 4; mt++)
#pragma unroll
            for (int nt = 0; nt < 4; nt++)
#pragma unroll
                for (int rr = 0; rr < 2; rr++)
#pragma unroll
                    for (int e = 0; e < 2; e++) {
                        int di = 2*mt + rr - (4*ck + nt) + 7;
                        int dj = g - (2*tig + e) + 7;
                        S[mt][nt][rr*2+e] = S[mt][nt][rr*2+e] * 0.17677669529663687f
                                          + sb[di*15 + dj];
                    }

        // online softmax per row
#pragma unroll
        for (int mt = 0; mt < 4; mt++)
#pragma unroll
            for (int rr = 0; rr < 2; rr++) {
                const int r8 = mt*2 + rr;
                float mloc = -1e30f;
#pragma unroll
                for (int nt = 0; nt < 4; nt++) {
                    mloc = fmaxf(mloc, S[mt][nt][rr*2]);
                    mloc = fmaxf(mloc, S[mt][nt][rr*2+1]);
                }
                mloc = fmaxf(mloc, __shfl_xor_sync(0xffffffffu, mloc, 1));
                mloc = fmaxf(mloc, __shfl_xor_sync(0xffffffffu, mloc, 2));
                float newm = fmaxf(mrow[r8], mloc);
                float fsc = __expf(mrow[r8] - newm);
                mrow[r8] = newm;
                float rsum = 0.f;
#pragma unroll
                for (int nt = 0; nt < 4; nt++) {
                    float p0 = __expf(S[mt][nt][rr*2]   - newm);
                    float p1 = __expf(S[mt][nt][rr*2+1] - newm);
                    S[mt][nt][rr*2] = p0; S[mt][nt][rr*2+1] = p1;
                    rsum += p0 + p1;
                }
                rsum += __shfl_xor_sync(0xffffffffu, rsum, 1);
                rsum += __shfl_xor_sync(0xffffffffu, rsum, 2);
                lrow[r8] = lrow[r8]*fsc + rsum;
#pragma unroll
                for (int nt2 = 0; nt2 < 4; nt2++) {
                    O[mt][nt2][rr*2]   *= fsc;
                    O[mt][nt2][rr*2+1] *= fsc;
                }
            }

        // O += P V   (P from S-fragments, V from transposed smem)
#pragma unroll
        for (int ks2 = 0; ks2 < 2; ks2++) {
            u32 bV[4][2];
#pragma unroll
            for (int nt2 = 0; nt2 < 4; nt2++) {
                bV[nt2][0] = *(const u32*)&Vt[nt2*8 + g][ck*32 + 16*ks2 + 2*tig];
                bV[nt2][1] = *(const u32*)&Vt[nt2*8 + g][ck*32 + 16*ks2 + 2*tig + 8];
            }
#pragma unroll
            for (int mt = 0; mt < 4; mt++) {
                u32 pa[4];
                pa[0] = packbf(S[mt][2*ks2  ][0], S[mt][2*ks2  ][1]);
                pa[1] = packbf(S[mt][2*ks2  ][2], S[mt][2*ks2  ][3]);
                pa[2] = packbf(S[mt][2*ks2+1][0], S[mt][2*ks2+1][1]);
                pa[3] = packbf(S[mt][2*ks2+1][2], S[mt][2*ks2+1][3]);
#pragma unroll
                for (int nt2 = 0; nt2 < 4; nt2++)
                    mma_bf16(O[mt][nt2], pa, bV[nt2]);
            }
        }
    }

    // normalize + store
    float invl[8];
#pragma unroll
    for (int r = 0; r < 8; r++) invl[r] = 1.f / lrow[r];
    __nv_bfloat16* ob = o + (size_t)win * 64 * 256 + h * 32;
#pragma unroll
    for (int mt = 0; mt < 4; mt++)
#pragma unroll
        for (int nt2 = 0; nt2 < 4; nt2++) {
            __nv_bfloat16* p0 = ob + (size_t)(mt*16 + g)*256 + nt2*8 + 2*tig;
            *(u32*)(p0)         = packbf(O[mt][nt2][0]*invl[2*mt],   O[mt][nt2][1]*invl[2*mt]);
            *(u32*)(p0 + 8*256) = packbf(O[mt][nt2][2]*invl[2*mt+1], O[mt][nt2][3]*invl[2*mt+1]);
        }
}

// -------------------- SE gate from completed pooled sums --------------------
__global__ void __launch_bounds__(256) k_pool_gate(const float* __restrict__ part,
                                                   const float* __restrict__ w1,
                                                   const float* __restrict__ b1,
                                                   const float* __restrict__ w2,
                                                   const float* __restrict__ b2,
                                                   float* __restrict__ gate) {
    int b = blockIdx.x;
    float pooled = part[b*256 + threadIdx.x] * (1.f / (float)TOK_PER_B);
    __shared__ float sp[256];
    __shared__ float hid[16];
    sp[threadIdx.x] = pooled;
    __syncthreads();
    if (threadIdx.x < 16) {
        float a = b1[threadIdx.x];
        for (int c = 0; c < 256; c++) a = fmaf(sp[c], w1[c*16 + threadIdx.x], a);
        hid[threadIdx.x] = fmaxf(a, 0.f);
    }
    __syncthreads();
    float g = b2[threadIdx.x];
#pragma unroll
    for (int j = 0; j < 16; j++) g = fmaf(hid[j], w2[j*256 + threadIdx.x], g);
    gate[b*256 + threadIdx.x] = 1.f / (1.f + __expf(-g));
}

// ---------------------------------------------------------------------------
extern "C" void kernel_launch(void* const* d_in, const int* in_sizes, int n_in,
                              void* d_out, int out_size) {
    const float* x      = (const float*)d_in[0];
    const float* n1_g   = (const float*)d_in[1];
    const float* n1_b   = (const float*)d_in[2];
    const float* qkv_w  = (const float*)d_in[3];
    const float* qkv_b  = (const float*)d_in[4];
    const float* proj_w = (const float*)d_in[5];
    const float* proj_b = (const float*)d_in[6];
    const float* rel_b  = (const float*)d_in[7];
    const float* se_w1  = (const float*)d_in[8];
    const float* se_b1  = (const float*)d_in[9];
    const float* se_w2  = (const float*)d_in[10];
    const float* se_b2  = (const float*)d_in[11];
    const float* n3_g   = (const float*)d_in[12];
    const float* n3_b   = (const float*)d_in[13];
    const float* mlp_w1 = (const float*)d_in[14];
    const float* mlp_b1 = (const float*)d_in[15];
    const float* mlp_w2 = (const float*)d_in[16];
    const float* mlp_b2 = (const float*)d_in[17];
    float* out = (float*)d_out;

    float *wins, *hbuf, *big, *part, *gate, *wb;
    cudaGetSymbolAddress((void**)&wins, g_wins);
    cudaGetSymbolAddress((void**)&hbuf, g_h);
    cudaGetSymbolAddress((void**)&big,  g_big);
    cudaGetSymbolAddress((void**)&part, g_part);
    cudaGetSymbolAddress((void**)&gate, g_gate);
    cudaGetSymbolAddress((void**)&wb,   g_wb);

    __nv_bfloat16* wbf   = (__nv_bfloat16*)wb;
    __nv_bfloat16* qkvW  = wbf;            // [768,256]
    __nv_bfloat16* projW = wbf + 196608;   // [256,256]
    __nv_bfloat16* w1W   = wbf + 262144;   // [1024,256]
    __nv_bfloat16* w2W   = wbf + 524288;   // [256,1024]
    __nv_bfloat16* bigb  = (__nv_bfloat16*)big;
    __nv_bfloat16* hb    = (__nv_bfloat16*)hbuf;

    cudaFuncSetAttribute(k_gemm_smA, cudaFuncAttributeMaxDynamicSharedMemorySize, SMA_SMEM);
    cudaFuncSetAttribute(k_gemm_sA,  cudaFuncAttributeMaxDynamicSharedMemorySize, SA_SMEM);

    dim3 b328(32, 8);

    // 0. zero pooled sums; prep bf16 transposed weights
    cudaMemsetAsync(part, 0, 1024 * sizeof(float));
    k_wprep<<<dim3(24, 8),  b328>>>(qkv_w,  qkvW,  256, 768);
    k_wprep<<<dim3(8,  8),  b328>>>(proj_w, projW, 256, 256);
    k_wprep<<<dim3(32, 8),  b328>>>(mlp_w1, w1W,   256, 1024);
    k_wprep<<<dim3(8,  32), b328>>>(mlp_w2, w2W,   1024, 256);

    dim3 gtr(WW_/32, HH, BATCH*8);
    // 1. window partition
    k_winpart<<<gtr, b328>>>(x, wins);
    // 2. QKV (LN1 fused) -> big bf16 [NTOK,768]
    k_gemm_smA<<<NTOK/128, 256, SMA_SMEM>>>(wins, 0, n1_g, n1_b, nullptr,
                                            qkvW, qkv_b, nullptr,
                                            bigb, 1, 0, 768, nullptr);
    // 3. attention (tensor cores) -> hb bf16 [NTOK,256]
    k_attn_tc<<<dim3(NWIN, 2), 128>>>(bigb, rel_b, hb);
    // 4. proj + residual(wins) -> wins fp32 (y), pooled sums -> part
    k_gemm_smA<<<NTOK/128, 256, SMA_SMEM>>>(hb, 1, nullptr, nullptr, nullptr,
                                            projW, proj_b, wins,
                                            wins, 0, 0, 256, part);
    // 5. SE gate
    k_pool_gate<<<BATCH, 256>>>(part, se_w1, se_b1, se_w2, se_b2, gate);
    // 6. MLP1 (gate+LN3 fused) + GELU -> big bf16 [NTOK,1024]
    k_gemm_smA<<<NTOK/128, 256, SMA_SMEM>>>(wins, 0, n3_g, n3_b, gate,
                                            w1W, mlp_b1, nullptr,
                                            bigb, 1, 1, 1024, nullptr);
    // 7. MLP2 + residual(y*gate) -> hbuf fp32
    k_gemm_sA<<<NTOK/128, 256, SA_SMEM>>>(bigb, w2W, mlp_b2, wins, gate, hbuf);
    // 8. window reverse -> out
    k_winrev<<<gtr, b328>>>(hbuf, out);
}

// round 8
// speedup vs baseline: 3.7454x; 1.0639x over previous
#include <cuda_runtime.h>
#include <cuda_bf16.h>
#include <cstdint>
#include <math.h>

// ---------------------------------------------------------------------------
// HATBlock — Round 8: ldmatrix fragment loads in all GEMMs + attention V.
// (R7 + LDSM: 48 LDS.32 -> 12 LDSM.x4 per warp-Kchunk)
// B=4, C=256, H=W=192, WS=8, NH=8, HD=32
// ---------------------------------------------------------------------------

#define BATCH 4
#define DIM   256
#define HH    192
#define WW_   192
#define NWH   24
#define NWIN  (BATCH*NWH*NWH)   // 2304
#define NTOK  (NWIN*64)         // 147456
#define NH    8
#define TOK_PER_B (HH*WW_)      // 36864

typedef unsigned long long u64;
typedef unsigned int u32;

// -------------------- scratch (device globals; no runtime alloc) -----------
__device__ float g_wins[(size_t)NTOK*256];     // wins / y (fp32)
__device__ float g_h   [(size_t)NTOK*256];     // attn-out bf16 alias / final fp32
__device__ float g_big [(size_t)NTOK*512];     // qkv(768) / hidden(1024) as bf16
__device__ float g_part[1024];                 // pooled sums [B,256]
__device__ float g_gate[BATCH*256];
__device__ float g_wb  [786432/2];             // bf16 weights, transposed [N,K]

__device__ __forceinline__ float gelu_exact(float x) {
    return 0.5f * x * (1.0f + erff(x * 0.70710678118654752f));
}

__device__ __forceinline__ void cp_async16(void* smem, const void* gmem) {
    unsigned s = (unsigned)__cvta_generic_to_shared(smem);
    asm volatile("cp.async.ca.shared.global [%0], [%1], 16;" :: "r"(s), "l"(gmem));
}
__device__ __forceinline__ void cp_commit() { asm volatile("cp.async.commit_group;"); }
__device__ __forceinline__ void cp_wait2()  { asm volatile("cp.async.wait_group 2;" ::: "memory"); }

__device__ __forceinline__ void mma_bf16(float* c, const u32* a, const u32* b) {
    asm volatile(
        "mma.sync.aligned.m16n8k16.row.col.f32.bf16.bf16.f32 "
        "{%0,%1,%2,%3},{%4,%5,%6,%7},{%8,%9},{%0,%1,%2,%3};"
        : "+f"(c[0]), "+f"(c[1]), "+f"(c[2]), "+f"(c[3])
        : "r"(a[0]), "r"(a[1]), "r"(a[2]), "r"(a[3]), "r"(b[0]), "r"(b[1]));
}

__device__ __forceinline__ void ldsm4(u32& r0, u32& r1, u32& r2, u32& r3, u32 addr) {
    asm volatile("ldmatrix.sync.aligned.m8n8.x4.shared.b16 {%0,%1,%2,%3}, [%4];"
                 : "=r"(r0), "=r"(r1), "=r"(r2), "=r"(r3) : "r"(addr));
}

__device__ __forceinline__ u32 packbf(float a, float b) {
    __nv_bfloat162 t = __float22bfloat162_rn(make_float2(a, b));
    return *(u32*)&t;
}

// -------------------- weight prep: fp32 [K,N] -> bf16 [N,K] ----------------
__global__ void k_wprep(const float* __restrict__ in, __nv_bfloat16* __restrict__ out,
                        int K, int N) {
    __shared__ float tile[32][33];
    int n0 = blockIdx.x * 32, k0 = blockIdx.y * 32;
    for (int r = threadIdx.y; r < 32; r += 8)
        tile[r][threadIdx.x] = in[(size_t)(k0 + r) * N + n0 + threadIdx.x];
    __syncthreads();
    for (int r = threadIdx.y; r < 32; r += 8)
        out[(size_t)(n0 + r) * K + k0 + threadIdx.x] = __float2bfloat16_rn(tile[threadIdx.x][r]);
}

// -------------------- window partition: x[B,C,H,W] -> wins[t,c] ------------
__global__ void k_winpart(const float* __restrict__ x, float* __restrict__ wins) {
    int w0 = blockIdx.x * 32, hh = blockIdx.y;
    int b = blockIdx.z >> 3, c0 = (blockIdx.z & 7) * 32;
    __shared__ float tile[32][33];
    for (int cc = threadIdx.y; cc < 32; cc += 8)
        tile[cc][threadIdx.x] =
            x[(((size_t)b*256 + c0 + cc)*HH + hh)*WW_ + w0 + threadIdx.x];
    __syncthreads();
    int hw = hh >> 3, i = hh & 7;
    for (int wi = threadIdx.y; wi < 32; wi += 8) {
        int w = w0 + wi, ww = w >> 3, j = w & 7;
        size_t t = (((size_t)b*NWH + hw)*NWH + ww)*64 + i*8 + j;
        wins[t*256 + c0 + threadIdx.x] = tile[threadIdx.x][wi];
    }
}

// -------------------- window reverse: z[t,c] -> out[B,C,H,W] ---------------
__global__ void k_winrev(const float* __restrict__ z, float* __restrict__ out) {
    int w0 = blockIdx.x * 32, hh = blockIdx.y;
    int b = blockIdx.z >> 3, c0 = (blockIdx.z & 7) * 32;
    __shared__ float tile[32][33];
    int hw = hh >> 3, i = hh & 7;
    for (int wi = threadIdx.y; wi < 32; wi += 8) {
        int w = w0 + wi, ww = w >> 3, j = w & 7;
        size_t t = (((size_t)b*NWH + hw)*NWH + ww)*64 + i*8 + j;
        tile[wi][threadIdx.x] = z[t*256 + c0 + threadIdx.x];
    }
    __syncthreads();
    for (int cc = threadIdx.y; cc < 32; cc += 8)
        out[(((size_t)b*256 + c0 + cc)*HH + hh)*WW_ + w0 + threadIdx.x] =
            tile[threadIdx.x][cc];
}

// ============================================================================
// GEMM 1: A cached in smem bf16 (optionally with fused gate+LN from fp32 gmem).
// 256 threads = 8 warps (4 m x 2 n), warp tile 32x64, K chunk 32, 4-stage B.
// Fragment loads via ldmatrix.x4 (conflict-free strides verified).
// ============================================================================
#define AB_STR 264
#define B_STR  40
#define SMA_BR 67584
#define SMA_SCOL 108544
#define SMA_SMEM 109056

__global__ void __launch_bounds__(256, 2)
k_gemm_smA(const void* __restrict__ Ain, int a_bf16,
           const float* __restrict__ lng, const float* __restrict__ lnb,
           const float* __restrict__ gate,
           const __nv_bfloat16* __restrict__ Wt,
           const float* __restrict__ bias,
           const float* __restrict__ R,
           void* __restrict__ Cout, int c_bf16, int act,
           int Nfull, float* __restrict__ pool)
{
    extern __shared__ char smem[];
    __nv_bfloat16* Ab = (__nv_bfloat16*)smem;
    char*  Bring = smem + SMA_BR;
    float* scol = (float*)(smem + SMA_SCOL);
    const u32 sbase = (u32)__cvta_generic_to_shared(smem);

    const int tid = threadIdx.x, lane = tid & 31, wid = tid >> 5;
    const int g = lane >> 2, tig = lane & 3;
    const int arow = (wid & 3) * 32;
    const int bcol = (wid >> 2) * 64;
    const int m0 = blockIdx.x * 128;
    const int b  = m0 / TOK_PER_B;

    // ldmatrix lane offsets
    const int a_dr = (lane & 7) | (((lane >> 3) & 1) << 3);   // row 0..15
    const int a_dk = (lane >> 4) << 3;                        // k 0 or 8
    const int quad = lane >> 3;
    const int b_dc = (lane & 7) + ((quad & 2) ? 8 : 0);       // col within pair
    const int b_dk = (quad & 1) << 3;

    // ---- load A ----
    if (a_bf16) {
        const __nv_bfloat16* Ag = (const __nv_bfloat16*)Ain + (size_t)m0 * 256;
#pragma unroll
        for (int i = 0; i < 16; i++) {
            int idx = tid + 256*i;
            int r = idx >> 5, c8 = idx & 31;
            cp_async16(Ab + r*AB_STR + c8*8, Ag + (size_t)r*256 + c8*8);
        }
        cp_commit();
    } else {
        const float* Ag = (const float*)Ain + (size_t)m0 * 256;
        const float* gp = gate ? (gate + b*256) : nullptr;
        float gv[8], lg[8], lb[8];
#pragma unroll
        for (int j = 0; j < 8; j++) {
            int c = lane*8 + j;
            gv[j] = gp ? gp[c] : 1.f;
            lg[j] = lng[c]; lb[j] = lnb[c];
        }
#pragma unroll 1
        for (int i = 0; i < 16; i++) {
            int r = wid*16 + i;
            const float4* rp = (const float4*)(Ag + (size_t)r * 256 + lane*8);
            float4 va = rp[0], vb = rp[1];
            float v[8] = {va.x, va.y, va.z, va.w, vb.x, vb.y, vb.z, vb.w};
            float s = 0.f, s2 = 0.f;
#pragma unroll
            for (int j = 0; j < 8; j++) {
                v[j] *= gv[j]; s += v[j]; s2 += v[j]*v[j];
            }
#pragma unroll
            for (int o = 16; o; o >>= 1) {
                s  += __shfl_xor_sync(0xffffffffu, s,  o);
                s2 += __shfl_xor_sync(0xffffffffu, s2, o);
            }
            float mean = s * (1.f/256.f);
            float var  = s2 * (1.f/256.f) - mean*mean;
            float inv  = rsqrtf(var + 1e-5f);
#pragma unroll
            for (int k = 0; k < 4; k++) {
                float n0 = (v[2*k  ]-mean)*inv*lg[2*k  ] + lb[2*k  ];
                float n1 = (v[2*k+1]-mean)*inv*lg[2*k+1] + lb[2*k+1];
                *(u32*)&Ab[r*AB_STR + lane*8 + 2*k] = packbf(n0, n1);
            }
        }
        __syncthreads();
    }

    const int NY = Nfull >> 7;
    const int KT = 8;
    const int TOT = NY * KT;

    auto fillB = [&](int c) {
        int ny2 = c >> 3, kt2 = c & 7, st = c & 3;
        __nv_bfloat16* Bs = (__nv_bfloat16*)(Bring + st*10240);
        const __nv_bfloat16* Wg = Wt + (size_t)(ny2*128) * 256 + kt2*32;
#pragma unroll
        for (int i = 0; i < 2; i++) {
            int idx = tid + 256*i;
            int row = idx >> 2, seg = idx & 3;
            cp_async16(Bs + row*B_STR + seg*8, Wg + (size_t)row*256 + seg*8);
        }
        cp_commit();
    };
    fillB(0); fillB(1); fillB(2);

    int ci = 0;
    for (int ny = 0; ny < NY; ny++) {
        float acc[2][8][4];
#pragma unroll
        for (int i = 0; i < 2; i++)
#pragma unroll
            for (int j = 0; j < 8; j++)
#pragma unroll
                for (int q = 0; q < 4; q++) acc[i][j][q] = 0.f;

        for (int kt = 0; kt < KT; kt++, ci++) {
            cp_wait2();
            __syncthreads();
            const u32 bsb = sbase + SMA_BR + (u32)(ci & 3)*10240;
#pragma unroll
            for (int ks = 0; ks < 2; ks++) {
                const int kb = kt*32 + ks*16;
                u32 af[2][4], bf[8][2];
#pragma unroll
                for (int mt = 0; mt < 2; mt++) {
                    u32 aaddr = sbase + (u32)(((arow + mt*16 + a_dr)*AB_STR + kb + a_dk) * 2);
                    ldsm4(af[mt][0], af[mt][1], af[mt][2], af[mt][3], aaddr);
                }
#pragma unroll
                for (int p = 0; p < 4; p++) {
                    u32 baddr = bsb + (u32)(((bcol + p*16 + b_dc)*B_STR + ks*16 + b_dk) * 2);
                    ldsm4(bf[2*p][0], bf[2*p][1], bf[2*p+1][0], bf[2*p+1][1], baddr);
                }
#pragma unroll
                for (int mt = 0; mt < 2; mt++)
#pragma unroll
                    for (int nt = 0; nt < 8; nt++)
                        mma_bf16(acc[mt][nt], af[mt], bf[nt]);
            }
            if (ci + 3 < TOT) fillB(ci + 3);
            else cp_commit();
        }

        const int ncol0 = ny * 128;
        if (c_bf16) {
            __nv_bfloat16* Cb = (__nv_bfloat16*)Cout;
#pragma unroll
            for (int nt = 0; nt < 8; nt++) {
                int colG = ncol0 + bcol + nt*8 + 2*tig;
                float b0 = bias[colG], b1 = bias[colG + 1];
#pragma unroll
                for (int mt = 0; mt < 2; mt++) {
                    size_t r0 = (size_t)m0 + arow + mt*16 + g;
                    size_t r1 = r0 + 8;
                    float v00 = acc[mt][nt][0] + b0, v01 = acc[mt][nt][1] + b1;
                    float v10 = acc[mt][nt][2] + b0, v11 = acc[mt][nt][3] + b1;
                    if (act) {
                        v00 = gelu_exact(v00); v01 = gelu_exact(v01);
                        v10 = gelu_exact(v10); v11 = gelu_exact(v11);
                    }
                    *(u32*)((__nv_bfloat16*)Cb + r0*Nfull + colG) = packbf(v00, v01);
                    *(u32*)((__nv_bfloat16*)Cb + r1*Nfull + colG) = packbf(v10, v11);
                }
            }
        } else {
            float* Cf = (float*)Cout;
            float psum[8][2];
#pragma unroll
            for (int nt = 0; nt < 8; nt++) { psum[nt][0] = 0.f; psum[nt][1] = 0.f; }
#pragma unroll
            for (int nt = 0; nt < 8; nt++) {
                int colG = ncol0 + bcol + nt*8 + 2*tig;
                float b0 = bias[colG], b1 = bias[colG + 1];
#pragma unroll
                for (int mt = 0; mt < 2; mt++) {
                    size_t r0 = (size_t)m0 + arow + mt*16 + g;
                    size_t r1 = r0 + 8;
                    float2 q0 = *(const float2*)(R + r0*Nfull + colG);
                    float2 q1 = *(const float2*)(R + r1*Nfull + colG);
                    float v00 = acc[mt][nt][0] + b0 + q0.x, v01 = acc[mt][nt][1] + b1 + q0.y;
                    float v10 = acc[mt][nt][2] + b0 + q1.x, v11 = acc[mt][nt][3] + b1 + q1.y;
                    *(float2*)(Cf + r0*Nfull + colG) = make_float2(v00, v01);
                    *(float2*)(Cf + r1*Nfull + colG) = make_float2(v10, v11);
                    psum[nt][0] += v00 + v10; psum[nt][1] += v01 + v11;
                }
            }
            if (pool) {
                __syncthreads();
                if (tid < 128) scol[tid] = 0.f;
                __syncthreads();
#pragma unroll
                for (int nt = 0; nt < 8; nt++) {
                    int colL = bcol + nt*8 + 2*tig;
                    atomicAdd(&scol[colL],     psum[nt][0]);
                    atomicAdd(&scol[colL + 1], psum[nt][1]);
                }
                __syncthreads();
                if (tid < 128) atomicAdd(pool + b*256 + ncol0 + tid, scol[tid]);
                __syncthreads();
            }
        }
    }
}

// ============================================================================
// GEMM 2 (MLP2): A bf16 streamed [M,1024], Wt bf16 [256,1024], N-loop (2).
// Fragment loads via ldmatrix.x4.
// ============================================================================
#define SA_SMEM 81920
__global__ void __launch_bounds__(256, 2)
k_gemm_sA(const __nv_bfloat16* __restrict__ Ain,
          const __nv_bfloat16* __restrict__ Wt,
          const float* __restrict__ bias,
          const float* __restrict__ R,
          const float* __restrict__ gate,
          float* __restrict__ Cout)
{
    extern __shared__ char smem[];
    const u32 sbase = (u32)__cvta_generic_to_shared(smem);
    const int tid = threadIdx.x, lane = tid & 31, wid = tid >> 5;
    const int g = lane >> 2, tig = lane & 3;
    const int arow = (wid & 3) * 32;
    const int bcol = (wid >> 2) * 64;
    const int m0 = blockIdx.x * 128;
    const int b  = m0 / TOK_PER_B;
    const int KT = 32, NY = 2, TOT = 64;

    const int a_dr = (lane & 7) | (((lane >> 3) & 1) << 3);
    const int a_dk = (lane >> 4) << 3;
    const int quad = lane >> 3;
    const int b_dc = (lane & 7) + ((quad & 2) ? 8 : 0);
    const int b_dk = (quad & 1) << 3;

    const __nv_bfloat16* Ag = Ain + (size_t)m0 * 1024;

    auto fillC = [&](int c) {
        int ny2 = c >> 5, kt2 = c & 31, st = c & 3;
        __nv_bfloat16* As = (__nv_bfloat16*)(smem + st*10240);
        __nv_bfloat16* Bs = (__nv_bfloat16*)(smem + 40960 + st*10240);
        const __nv_bfloat16* Wg = Wt + (size_t)(ny2*128) * 1024 + kt2*32;
        const __nv_bfloat16* Ac = Ag + kt2*32;
#pragma unroll
        for (int i = 0; i < 2; i++) {
            int idx = tid + 256*i;
            int row = idx >> 2, seg = idx & 3;
            cp_async16(As + row*B_STR + seg*8, Ac + (size_t)row*1024 + seg*8);
            cp_async16(Bs + row*B_STR + seg*8, Wg + (size_t)row*1024 + seg*8);
        }
        cp_commit();
    };
    fillC(0); fillC(1); fillC(2);

    int ci = 0;
    for (int ny = 0; ny < NY; ny++) {
        float acc[2][8][4];
#pragma unroll
        for (int i = 0; i < 2; i++)
#pragma unroll
            for (int j = 0; j < 8; j++)
#pragma unroll
                for (int q = 0; q < 4; q++) acc[i][j][q] = 0.f;

        for (int kt = 0; kt < KT; kt++, ci++) {
            cp_wait2();
            __syncthreads();
            int st = ci & 3;
            const u32 asb = sbase + (u32)st*10240;
            const u32 bsb = sbase + 40960u + (u32)st*10240;
#pragma unroll
            for (int ks = 0; ks < 2; ks++) {
                u32 af[2][4], bf[8][2];
#pragma unroll
                for (int mt = 0; mt < 2; mt++) {
                    u32 aaddr = asb + (u32)(((arow + mt*16 + a_dr)*B_STR + ks*16 + a_dk) * 2);
                    ldsm4(af[mt][0], af[mt][1], af[mt][2], af[mt][3], aaddr);
                }
#pragma unroll
                for (int p = 0; p < 4; p++) {
                    u32 baddr = bsb + (u32)(((bcol + p*16 + b_dc)*B_STR + ks*16 + b_dk) * 2);
                    ldsm4(bf[2*p][0], bf[2*p][1], bf[2*p+1][0], bf[2*p+1][1], baddr);
                }
#pragma unroll
                for (int mt = 0; mt < 2; mt++)
#pragma unroll
                    for (int nt = 0; nt < 8; nt++)
                        mma_bf16(acc[mt][nt], af[mt], bf[nt]);
            }
            if (ci + 3 < TOT) fillC(ci + 3);
            else cp_commit();
        }

        const int ncol0 = ny * 128;
#pragma unroll
        for (int nt = 0; nt < 8; nt++) {
            int colG = ncol0 + bcol + nt*8 + 2*tig;
            float b0 = bias[colG], b1 = bias[colG + 1];
            float g0 = gate[b*256 + colG], g1 = gate[b*256 + colG + 1];
#pragma unroll
            for (int mt = 0; mt < 2; mt++) {
                size_t r0 = (size_t)m0 + arow + mt*16 + g;
                size_t r1 = r0 + 8;
                float2 q0 = *(const float2*)(R + r0*256 + colG);
                float2 q1 = *(const float2*)(R + r1*256 + colG);
                float v00 = acc[mt][nt][0] + b0 + q0.x*g0, v01 = acc[mt][nt][1] + b1 + q0.y*g1;
                float v10 = acc[mt][nt][2] + b0 + q1.x*g0, v11 = acc[mt][nt][3] + b1 + q1.y*g1;
                *(float2*)(Cout + r0*256 + colG) = make_float2(v00, v01);
                *(float2*)(Cout + r1*256 + colG) = make_float2(v10, v11);
            }
        }
    }
}

// ============================================================================
// Tensor-core window attention: one warp per (window, head).
// ============================================================================
__global__ void __launch_bounds__(128) k_attn_tc(const __nv_bfloat16* __restrict__ qkv,
                                                 const float* __restrict__ rel_bias,
                                                 __nv_bfloat16* __restrict__ o) {
    __shared__ __align__(16) __nv_bfloat16 VtAll[4][32][72];
    __shared__ float sbAll[4][226];

    const int lane = threadIdx.x & 31;
    const int wid  = threadIdx.x >> 5;
    const int g = lane >> 2, tig = lane & 3;
    const int win = blockIdx.x;
    const int h = blockIdx.y * 4 + wid;

    __nv_bfloat16 (*Vt)[72] = VtAll[wid];
    float* sb = sbAll[wid];
    const u32 vtb = (u32)__cvta_generic_to_shared(&VtAll[wid][0][0]);

    const int quad = lane >> 3;
    const int v_dc = (lane & 7) + ((quad & 2) ? 8 : 0);
    const int v_dk = (quad & 1) << 3;

    const __nv_bfloat16* qw = qkv + (size_t)win * 64 * 768 + h * 32;
    const __nv_bfloat16* kw = qw + 256;
    const __nv_bfloat16* vw = qw + 512;

    for (int r = lane; r < 225; r += 32) sb[r] = rel_bias[r*NH + h];

#pragma unroll
    for (int i = 0; i < 32; i++) {
        int idx = lane + 32*i;
        int n = idx >> 4, dp = idx & 15;
        u32 u = *(const u32*)(vw + (size_t)n*768 + 2*dp);
        __nv_bfloat162 v2 = *(__nv_bfloat162*)&u;
        Vt[2*dp  ][n] = v2.x;
        Vt[2*dp+1][n] = v2.y;
    }
    __syncwarp();

    float O[4][4][4];
#pragma unroll
    for (int a = 0; a < 4; a++)
#pragma unroll
        for (int bq = 0; bq < 4; bq++)
#pragma unroll
            for (int c = 0; c < 4; c++) O[a][bq][c] = 0.f;
    float mrow[8], lrow[8];
#pragma unroll
    for (int r = 0; r < 8; r++) { mrow[r] = -1e30f; lrow[r] = 0.f; }

#pragma unroll 1
    for (int ck = 0; ck < 2; ck++) {
        float S[4][4][4];
#pragma unroll
        for (int a = 0; a < 4; a++)
#pragma unroll
            for (int bq = 0; bq < 4; bq++)
#pragma unroll
                for (int c = 0; c < 4; c++) S[a][bq][c] = 0.f;

#pragma unroll
        for (int ks = 0; ks < 2; ks++) {
            const int kc = 16*ks + 2*tig;
            u32 aQ[4][4], bK[4][2];
#pragma unroll
            for (int mt = 0; mt < 4; mt++) {
                const __nv_bfloat16* q0 = qw + (size_t)(mt*16 + g)*768 + kc;
                aQ[mt][0] = *(const u32*)(q0);
                aQ[mt][1] = *(const u32*)(q0 + 8*768);
                aQ[mt][2] = *(const u32*)(q0 + 8);
                aQ[mt][3] = *(const u32*)(q0 + 8*768 + 8);
            }
#pragma unroll
            for (int nt = 0; nt < 4; nt++) {
                const __nv_bfloat16* k0 = kw + (size_t)(ck*32 + nt*8 + g)*768 + kc;
                bK[nt][0] = *(const u32*)(k0);
                bK[nt][1] = *(const u32*)(k0 + 8);
            }
#pragma unroll
            for (int mt = 0; mt < 4; mt++)
#pragma unroll
                for (int nt = 0; nt < 4; nt++)
                    mma_bf16(S[mt][nt], aQ[mt], bK[nt]);
        }

#pragma unroll
        for (int mt = 0; mt < 4; mt++)
#pragma unroll
            for (int nt = 0; nt < 4; nt++)
#pragma unroll
                for (int rr = 0; rr < 2; rr++)
#pragma unroll
                    for (int e = 0; e < 2; e++) {
                        int di = 2*mt + rr - (4*ck + nt) + 7;
                        int dj = g - (2*tig + e) + 7;
                        S[mt][nt][rr*2+e] = S[mt][nt][rr*2+e] * 0.17677669529663687f
                                          + sb[di*15 + dj];
                    }

#pragma unroll
        for (int mt = 0; mt < 4; mt++)
#pragma unroll
            for (int rr = 0; rr < 2; rr++) {
                const int r8 = mt*2 + rr;
                float mloc = -1e30f;
#pragma unroll
                for (int nt = 0; nt < 4; nt++) {
                    mloc = fmaxf(mloc, S[mt][nt][rr*2]);
                    mloc = fmaxf(mloc, S[mt][nt][rr*2+1]);
                }
                mloc = fmaxf(mloc, __shfl_xor_sync(0xffffffffu, mloc, 1));
                mloc = fmaxf(mloc, __shfl_xor_sync(0xffffffffu, mloc, 2));
                float newm = fmaxf(mrow[r8], mloc);
                float fsc = __expf(mrow[r8] - newm);
                mrow[r8] = newm;
                float rsum = 0.f;
#pragma unroll
                for (int nt = 0; nt < 4; nt++) {
                    float p0 = __expf(S[mt][nt][rr*2]   - newm);
                    float p1 = __expf(S[mt][nt][rr*2+1] - newm);
                    S[mt][nt][rr*2] = p0; S[mt][nt][rr*2+1] = p1;
                    rsum += p0 + p1;
                }
                rsum += __shfl_xor_sync(0xffffffffu, rsum, 1);
                rsum += __shfl_xor_sync(0xffffffffu, rsum, 2);
                lrow[r8] = lrow[r8]*fsc + rsum;
#pragma unroll
                for (int nt2 = 0; nt2 < 4; nt2++) {
                    O[mt][nt2][rr*2]   *= fsc;
                    O[mt][nt2][rr*2+1] *= fsc;
                }
            }

#pragma unroll
        for (int ks2 = 0; ks2 < 2; ks2++) {
            u32 bV[4][2];
#pragma unroll
            for (int p = 0; p < 2; p++) {
                u32 vaddr = vtb + (u32)(((p*16 + v_dc)*72 + ck*32 + ks2*16 + v_dk) * 2);
                ldsm4(bV[2*p][0], bV[2*p][1], bV[2*p+1][0], bV[2*p+1][1], vaddr);
            }
#pragma unroll
            for (int mt = 0; mt < 4; mt++) {
                u32 pa[4];
                pa[0] = packbf(S[mt][2*ks2  ][0], S[mt][2*ks2  ][1]);
                pa[1] = packbf(S[mt][2*ks2  ][2], S[mt][2*ks2  ][3]);
                pa[2] = packbf(S[mt][2*ks2+1][0], S[mt][2*ks2+1][1]);
                pa[3] = packbf(S[mt][2*ks2+1][2], S[mt][2*ks2+1][3]);
#pragma unroll
                for (int nt2 = 0; nt2 < 4; nt2++)
                    mma_bf16(O[mt][nt2], pa, bV[nt2]);
            }
        }
    }

    float invl[8];
#pragma unroll
    for (int r = 0; r < 8; r++) invl[r] = 1.f / lrow[r];
    __nv_bfloat16* ob = o + (size_t)win * 64 * 256 + h * 32;
#pragma unroll
    for (int mt = 0; mt < 4; mt++)
#pragma unroll
        for (int nt2 = 0; nt2 < 4; nt2++) {
            __nv_bfloat16* p0 = ob + (size_t)(mt*16 + g)*256 + nt2*8 + 2*tig;
            *(u32*)(p0)         = packbf(O[mt][nt2][0]*invl[2*mt],   O[mt][nt2][1]*invl[2*mt]);
            *(u32*)(p0 + 8*256) = packbf(O[mt][nt2][2]*invl[2*mt+1], O[mt][nt2][3]*invl[2*mt+1]);
        }
}

// -------------------- SE gate from completed pooled sums --------------------
__global__ void __launch_bounds__(256) k_pool_gate(const float* __restrict__ part,
                                                   const float* __restrict__ w1,
                                                   const float* __restrict__ b1,
                                                   const float* __restrict__ w2,
                                                   const float* __restrict__ b2,
                                                   float* __restrict__ gate) {
    int b = blockIdx.x;
    float pooled = part[b*256 + threadIdx.x] * (1.f / (float)TOK_PER_B);
    __shared__ float sp[256];
    __shared__ float hid[16];
    sp[threadIdx.x] = pooled;
    __syncthreads();
    if (threadIdx.x < 16) {
        float a = b1[threadIdx.x];
        for (int c = 0; c < 256; c++) a = fmaf(sp[c], w1[c*16 + threadIdx.x], a);
        hid[threadIdx.x] = fmaxf(a, 0.f);
    }
    __syncthreads();
    float g = b2[threadIdx.x];
#pragma unroll
    for (int j = 0; j < 16; j++) g = fmaf(hid[j], w2[j*256 + threadIdx.x], g);
    gate[b*256 + threadIdx.x] = 1.f / (1.f + __expf(-g));
}

// ---------------------------------------------------------------------------
extern "C" void kernel_launch(void* const* d_in, const int* in_sizes, int n_in,
                              void* d_out, int out_size) {
    const float* x      = (const float*)d_in[0];
    const float* n1_g   = (const float*)d_in[1];
    const float* n1_b   = (const float*)d_in[2];
    const float* qkv_w  = (const float*)d_in[3];
    const float* qkv_b  = (const float*)d_in[4];
    const float* proj_w = (const float*)d_in[5];
    const float* proj_b = (const float*)d_in[6];
    const float* rel_b  = (const float*)d_in[7];
    const float* se_w1  = (const float*)d_in[8];
    const float* se_b1  = (const float*)d_in[9];
    const float* se_w2  = (const float*)d_in[10];
    const float* se_b2  = (const float*)d_in[11];
    const float* n3_g   = (const float*)d_in[12];
    const float* n3_b   = (const float*)d_in[13];
    const float* mlp_w1 = (const float*)d_in[14];
    const float* mlp_b1 = (const float*)d_in[15];
    const float* mlp_w2 = (const float*)d_in[16];
    const float* mlp_b2 = (const float*)d_in[17];
    float* out = (float*)d_out;

    float *wins, *hbuf, *big, *part, *gate, *wb;
    cudaGetSymbolAddress((void**)&wins, g_wins);
    cudaGetSymbolAddress((void**)&hbuf, g_h);
    cudaGetSymbolAddress((void**)&big,  g_big);
    cudaGetSymbolAddress((void**)&part, g_part);
    cudaGetSymbolAddress((void**)&gate, g_gate);
    cudaGetSymbolAddress((void**)&wb,   g_wb);

    __nv_bfloat16* wbf   = (__nv_bfloat16*)wb;
    __nv_bfloat16* qkvW  = wbf;            // [768,256]
    __nv_bfloat16* projW = wbf + 196608;   // [256,256]
    __nv_bfloat16* w1W   = wbf + 262144;   // [1024,256]
    __nv_bfloat16* w2W   = wbf + 524288;   // [256,1024]
    __nv_bfloat16* bigb  = (__nv_bfloat16*)big;
    __nv_bfloat16* hb    = (__nv_bfloat16*)hbuf;

    cudaFuncSetAttribute(k_gemm_smA, cudaFuncAttributeMaxDynamicSharedMemorySize, SMA_SMEM);
    cudaFuncSetAttribute(k_gemm_sA,  cudaFuncAttributeMaxDynamicSharedMemorySize, SA_SMEM);

    dim3 b328(32, 8);

    cudaMemsetAsync(part, 0, 1024 * sizeof(float));
    k_wprep<<<dim3(24, 8),  b328>>>(qkv_w,  qkvW,  256, 768);
    k_wprep<<<dim3(8,  8),  b328>>>(proj_w, projW, 256, 256);
    k_wprep<<<dim3(32, 8),  b328>>>(mlp_w1, w1W,   256, 1024);
    k_wprep<<<dim3(8,  32), b328>>>(mlp_w2, w2W,   1024, 256);

    dim3 gtr(WW_/32, HH, BATCH*8);
    k_winpart<<<gtr, b328>>>(x, wins);
    k_gemm_smA<<<NTOK/128, 256, SMA_SMEM>>>(wins, 0, n1_g, n1_b, nullptr,
                                            qkvW, qkv_b, nullptr,
                                            bigb, 1, 0, 768, nullptr);
    k_attn_tc<<<dim3(NWIN, 2), 128>>>(bigb, rel_b, hb);
    k_gemm_smA<<<NTOK/128, 256, SMA_SMEM>>>(hb, 1, nullptr, nullptr, nullptr,
                                            projW, proj_b, wins,
                                            wins, 0, 0, 256, part);
    k_pool_gate<<<BATCH, 256>>>(part, se_w1, se_b1, se_w2, se_b2, gate);
    k_gemm_smA<<<NTOK/128, 256, SMA_SMEM>>>(wins, 0, n3_g, n3_b, gate,
                                            w1W, mlp_b1, nullptr,
                                            bigb, 1, 1, 1024, nullptr);
    k_gemm_sA<<<NTOK/128, 256, SA_SMEM>>>(bigb, w2W, mlp_b2, wins, gate, hbuf);
    k_winrev<<<gtr, b328>>>(hbuf, out);
}

// round 9
// speedup vs baseline: 3.7689x; 1.0063x over previous
#include <cuda_runtime.h>
#include <cuda_bf16.h>
#include <cstdint>
#include <math.h>

// ---------------------------------------------------------------------------
// HATBlock — Round 9: R8 + launch reorder (ncu captures QKV GEMM) +
// attention Q-fragment hoist.
// B=4, C=256, H=W=192, WS=8, NH=8, HD=32
// ---------------------------------------------------------------------------

#define BATCH 4
#define DIM   256
#define HH    192
#define WW_   192
#define NWH   24
#define NWIN  (BATCH*NWH*NWH)   // 2304
#define NTOK  (NWIN*64)         // 147456
#define NH    8
#define TOK_PER_B (HH*WW_)      // 36864

typedef unsigned long long u64;
typedef unsigned int u32;

// -------------------- scratch (device globals; no runtime alloc) -----------
__device__ float g_wins[(size_t)NTOK*256];     // wins / y (fp32)
__device__ float g_h   [(size_t)NTOK*256];     // attn-out bf16 alias / final fp32
__device__ float g_big [(size_t)NTOK*512];     // qkv(768) / hidden(1024) as bf16
__device__ float g_part[1024];                 // pooled sums [B,256]
__device__ float g_gate[BATCH*256];
__device__ float g_wb  [786432/2];             // bf16 weights, transposed [N,K]

__device__ __forceinline__ float gelu_exact(float x) {
    return 0.5f * x * (1.0f + erff(x * 0.70710678118654752f));
}

__device__ __forceinline__ void cp_async16(void* smem, const void* gmem) {
    unsigned s = (unsigned)__cvta_generic_to_shared(smem);
    asm volatile("cp.async.ca.shared.global [%0], [%1], 16;" :: "r"(s), "l"(gmem));
}
__device__ __forceinline__ void cp_commit() { asm volatile("cp.async.commit_group;"); }
__device__ __forceinline__ void cp_wait2()  { asm volatile("cp.async.wait_group 2;" ::: "memory"); }

__device__ __forceinline__ void mma_bf16(float* c, const u32* a, const u32* b) {
    asm volatile(
        "mma.sync.aligned.m16n8k16.row.col.f32.bf16.bf16.f32 "
        "{%0,%1,%2,%3},{%4,%5,%6,%7},{%8,%9},{%0,%1,%2,%3};"
        : "+f"(c[0]), "+f"(c[1]), "+f"(c[2]), "+f"(c[3])
        : "r"(a[0]), "r"(a[1]), "r"(a[2]), "r"(a[3]), "r"(b[0]), "r"(b[1]));
}

__device__ __forceinline__ void ldsm4(u32& r0, u32& r1, u32& r2, u32& r3, u32 addr) {
    asm volatile("ldmatrix.sync.aligned.m8n8.x4.shared.b16 {%0,%1,%2,%3}, [%4];"
                 : "=r"(r0), "=r"(r1), "=r"(r2), "=r"(r3) : "r"(addr));
}

__device__ __forceinline__ u32 packbf(float a, float b) {
    __nv_bfloat162 t = __float22bfloat162_rn(make_float2(a, b));
    return *(u32*)&t;
}

// -------------------- weight prep: fp32 [K,N] -> bf16 [N,K] ----------------
__global__ void k_wprep(const float* __restrict__ in, __nv_bfloat16* __restrict__ out,
                        int K, int N) {
    __shared__ float tile[32][33];
    int n0 = blockIdx.x * 32, k0 = blockIdx.y * 32;
    for (int r = threadIdx.y; r < 32; r += 8)
        tile[r][threadIdx.x] = in[(size_t)(k0 + r) * N + n0 + threadIdx.x];
    __syncthreads();
    for (int r = threadIdx.y; r < 32; r += 8)
        out[(size_t)(n0 + r) * K + k0 + threadIdx.x] = __float2bfloat16_rn(tile[threadIdx.x][r]);
}

// -------------------- window partition: x[B,C,H,W] -> wins[t,c] ------------
__global__ void k_winpart(const float* __restrict__ x, float* __restrict__ wins) {
    int w0 = blockIdx.x * 32, hh = blockIdx.y;
    int b = blockIdx.z >> 3, c0 = (blockIdx.z & 7) * 32;
    __shared__ float tile[32][33];
    for (int cc = threadIdx.y; cc < 32; cc += 8)
        tile[cc][threadIdx.x] =
            x[(((size_t)b*256 + c0 + cc)*HH + hh)*WW_ + w0 + threadIdx.x];
    __syncthreads();
    int hw = hh >> 3, i = hh & 7;
    for (int wi = threadIdx.y; wi < 32; wi += 8) {
        int w = w0 + wi, ww = w >> 3, j = w & 7;
        size_t t = (((size_t)b*NWH + hw)*NWH + ww)*64 + i*8 + j;
        wins[t*256 + c0 + threadIdx.x] = tile[threadIdx.x][wi];
    }
}

// -------------------- window reverse: z[t,c] -> out[B,C,H,W] ---------------
__global__ void k_winrev(const float* __restrict__ z, float* __restrict__ out) {
    int w0 = blockIdx.x * 32, hh = blockIdx.y;
    int b = blockIdx.z >> 3, c0 = (blockIdx.z & 7) * 32;
    __shared__ float tile[32][33];
    int hw = hh >> 3, i = hh & 7;
    for (int wi = threadIdx.y; wi < 32; wi += 8) {
        int w = w0 + wi, ww = w >> 3, j = w & 7;
        size_t t = (((size_t)b*NWH + hw)*NWH + ww)*64 + i*8 + j;
        tile[wi][threadIdx.x] = z[t*256 + c0 + threadIdx.x];
    }
    __syncthreads();
    for (int cc = threadIdx.y; cc < 32; cc += 8)
        out[(((size_t)b*256 + c0 + cc)*HH + hh)*WW_ + w0 + threadIdx.x] =
            tile[threadIdx.x][cc];
}

// ============================================================================
// GEMM 1: A cached in smem bf16 (optionally with fused gate+LN from fp32 gmem).
// 256 threads = 8 warps (4 m x 2 n), warp tile 32x64, K chunk 32, 4-stage B.
// Fragment loads via ldmatrix.x4 (conflict-free strides verified).
// ============================================================================
#define AB_STR 264
#define B_STR  40
#define SMA_BR 67584
#define SMA_SCOL 108544
#define SMA_SMEM 109056

__global__ void __launch_bounds__(256, 2)
k_gemm_smA(const void* __restrict__ Ain, int a_bf16,
           const float* __restrict__ lng, const float* __restrict__ lnb,
           const float* __restrict__ gate,
           const __nv_bfloat16* __restrict__ Wt,
           const float* __restrict__ bias,
           const float* __restrict__ R,
           void* __restrict__ Cout, int c_bf16, int act,
           int Nfull, float* __restrict__ pool)
{
    extern __shared__ char smem[];
    __nv_bfloat16* Ab = (__nv_bfloat16*)smem;
    char*  Bring = smem + SMA_BR;
    float* scol = (float*)(smem + SMA_SCOL);
    const u32 sbase = (u32)__cvta_generic_to_shared(smem);

    const int tid = threadIdx.x, lane = tid & 31, wid = tid >> 5;
    const int g = lane >> 2, tig = lane & 3;
    const int arow = (wid & 3) * 32;
    const int bcol = (wid >> 2) * 64;
    const int m0 = blockIdx.x * 128;
    const int b  = m0 / TOK_PER_B;

    const int a_dr = (lane & 7) | (((lane >> 3) & 1) << 3);
    const int a_dk = (lane >> 4) << 3;
    const int quad = lane >> 3;
    const int b_dc = (lane & 7) + ((quad & 2) ? 8 : 0);
    const int b_dk = (quad & 1) << 3;

    // ---- load A ----
    if (a_bf16) {
        const __nv_bfloat16* Ag = (const __nv_bfloat16*)Ain + (size_t)m0 * 256;
#pragma unroll
        for (int i = 0; i < 16; i++) {
            int idx = tid + 256*i;
            int r = idx >> 5, c8 = idx & 31;
            cp_async16(Ab + r*AB_STR + c8*8, Ag + (size_t)r*256 + c8*8);
        }
        cp_commit();
    } else {
        const float* Ag = (const float*)Ain + (size_t)m0 * 256;
        const float* gp = gate ? (gate + b*256) : nullptr;
        float gv[8], lg[8], lb[8];
#pragma unroll
        for (int j = 0; j < 8; j++) {
            int c = lane*8 + j;
            gv[j] = gp ? gp[c] : 1.f;
            lg[j] = lng[c]; lb[j] = lnb[c];
        }
#pragma unroll 1
        for (int i = 0; i < 16; i++) {
            int r = wid*16 + i;
            const float4* rp = (const float4*)(Ag + (size_t)r * 256 + lane*8);
            float4 va = rp[0], vb = rp[1];
            float v[8] = {va.x, va.y, va.z, va.w, vb.x, vb.y, vb.z, vb.w};
            float s = 0.f, s2 = 0.f;
#pragma unroll
            for (int j = 0; j < 8; j++) {
                v[j] *= gv[j]; s += v[j]; s2 += v[j]*v[j];
            }
#pragma unroll
            for (int o = 16; o; o >>= 1) {
                s  += __shfl_xor_sync(0xffffffffu, s,  o);
                s2 += __shfl_xor_sync(0xffffffffu, s2, o);
            }
            float mean = s * (1.f/256.f);
            float var  = s2 * (1.f/256.f) - mean*mean;
            float inv  = rsqrtf(var + 1e-5f);
#pragma unroll
            for (int k = 0; k < 4; k++) {
                float n0 = (v[2*k  ]-mean)*inv*lg[2*k  ] + lb[2*k  ];
                float n1 = (v[2*k+1]-mean)*inv*lg[2*k+1] + lb[2*k+1];
                *(u32*)&Ab[r*AB_STR + lane*8 + 2*k] = packbf(n0, n1);
            }
        }
        __syncthreads();
    }

    const int NY = Nfull >> 7;
    const int KT = 8;
    const int TOT = NY * KT;

    auto fillB = [&](int c) {
        int ny2 = c >> 3, kt2 = c & 7, st = c & 3;
        __nv_bfloat16* Bs = (__nv_bfloat16*)(Bring + st*10240);
        const __nv_bfloat16* Wg = Wt + (size_t)(ny2*128) * 256 + kt2*32;
#pragma unroll
        for (int i = 0; i < 2; i++) {
            int idx = tid + 256*i;
            int row = idx >> 2, seg = idx & 3;
            cp_async16(Bs + row*B_STR + seg*8, Wg + (size_t)row*256 + seg*8);
        }
        cp_commit();
    };
    fillB(0); fillB(1); fillB(2);

    int ci = 0;
    for (int ny = 0; ny < NY; ny++) {
        float acc[2][8][4];
#pragma unroll
        for (int i = 0; i < 2; i++)
#pragma unroll
            for (int j = 0; j < 8; j++)
#pragma unroll
                for (int q = 0; q < 4; q++) acc[i][j][q] = 0.f;

        for (int kt = 0; kt < KT; kt++, ci++) {
            cp_wait2();
            __syncthreads();
            const u32 bsb = sbase + SMA_BR + (u32)(ci & 3)*10240;
#pragma unroll
            for (int ks = 0; ks < 2; ks++) {
                const int kb = kt*32 + ks*16;
                u32 af[2][4], bf[8][2];
#pragma unroll
                for (int mt = 0; mt < 2; mt++) {
                    u32 aaddr = sbase + (u32)(((arow + mt*16 + a_dr)*AB_STR + kb + a_dk) * 2);
                    ldsm4(af[mt][0], af[mt][1], af[mt][2], af[mt][3], aaddr);
                }
#pragma unroll
                for (int p = 0; p < 4; p++) {
                    u32 baddr = bsb + (u32)(((bcol + p*16 + b_dc)*B_STR + ks*16 + b_dk) * 2);
                    ldsm4(bf[2*p][0], bf[2*p][1], bf[2*p+1][0], bf[2*p+1][1], baddr);
                }
#pragma unroll
                for (int mt = 0; mt < 2; mt++)
#pragma unroll
                    for (int nt = 0; nt < 8; nt++)
                        mma_bf16(acc[mt][nt], af[mt], bf[nt]);
            }
            if (ci + 3 < TOT) fillB(ci + 3);
            else cp_commit();
        }

        const int ncol0 = ny * 128;
        if (c_bf16) {
            __nv_bfloat16* Cb = (__nv_bfloat16*)Cout;
#pragma unroll
            for (int nt = 0; nt < 8; nt++) {
                int colG = ncol0 + bcol + nt*8 + 2*tig;
                float b0 = bias[colG], b1 = bias[colG + 1];
#pragma unroll
                for (int mt = 0; mt < 2; mt++) {
                    size_t r0 = (size_t)m0 + arow + mt*16 + g;
                    size_t r1 = r0 + 8;
                    float v00 = acc[mt][nt][0] + b0, v01 = acc[mt][nt][1] + b1;
                    float v10 = acc[mt][nt][2] + b0, v11 = acc[mt][nt][3] + b1;
                    if (act) {
                        v00 = gelu_exact(v00); v01 = gelu_exact(v01);
                        v10 = gelu_exact(v10); v11 = gelu_exact(v11);
                    }
                    *(u32*)((__nv_bfloat16*)Cb + r0*Nfull + colG) = packbf(v00, v01);
                    *(u32*)((__nv_bfloat16*)Cb + r1*Nfull + colG) = packbf(v10, v11);
                }
            }
        } else {
            float* Cf = (float*)Cout;
            float psum[8][2];
#pragma unroll
            for (int nt = 0; nt < 8; nt++) { psum[nt][0] = 0.f; psum[nt][1] = 0.f; }
#pragma unroll
            for (int nt = 0; nt < 8; nt++) {
                int colG = ncol0 + bcol + nt*8 + 2*tig;
                float b0 = bias[colG], b1 = bias[colG + 1];
#pragma unroll
                for (int mt = 0; mt < 2; mt++) {
                    size_t r0 = (size_t)m0 + arow + mt*16 + g;
                    size_t r1 = r0 + 8;
                    float2 q0 = *(const float2*)(R + r0*Nfull + colG);
                    float2 q1 = *(const float2*)(R + r1*Nfull + colG);
                    float v00 = acc[mt][nt][0] + b0 + q0.x, v01 = acc[mt][nt][1] + b1 + q0.y;
                    float v10 = acc[mt][nt][2] + b0 + q1.x, v11 = acc[mt][nt][3] + b1 + q1.y;
                    *(float2*)(Cf + r0*Nfull + colG) = make_float2(v00, v01);
                    *(float2*)(Cf + r1*Nfull + colG) = make_float2(v10, v11);
                    psum[nt][0] += v00 + v10; psum[nt][1] += v01 + v11;
                }
            }
            if (pool) {
                __syncthreads();
                if (tid < 128) scol[tid] = 0.f;
                __syncthreads();
#pragma unroll
                for (int nt = 0; nt < 8; nt++) {
                    int colL = bcol + nt*8 + 2*tig;
                    atomicAdd(&scol[colL],     psum[nt][0]);
                    atomicAdd(&scol[colL + 1], psum[nt][1]);
                }
                __syncthreads();
                if (tid < 128) atomicAdd(pool + b*256 + ncol0 + tid, scol[tid]);
                __syncthreads();
            }
        }
    }
}

// ============================================================================
// GEMM 2 (MLP2): A bf16 streamed [M,1024], Wt bf16 [256,1024], N-loop (2).
// ============================================================================
#define SA_SMEM 81920
__global__ void __launch_bounds__(256, 2)
k_gemm_sA(const __nv_bfloat16* __restrict__ Ain,
          const __nv_bfloat16* __restrict__ Wt,
          const float* __restrict__ bias,
          const float* __restrict__ R,
          const float* __restrict__ gate,
          float* __restrict__ Cout)
{
    extern __shared__ char smem[];
    const u32 sbase = (u32)__cvta_generic_to_shared(smem);
    const int tid = threadIdx.x, lane = tid & 31, wid = tid >> 5;
    const int g = lane >> 2, tig = lane & 3;
    const int arow = (wid & 3) * 32;
    const int bcol = (wid >> 2) * 64;
    const int m0 = blockIdx.x * 128;
    const int b  = m0 / TOK_PER_B;
    const int KT = 32, NY = 2, TOT = 64;

    const int a_dr = (lane & 7) | (((lane >> 3) & 1) << 3);
    const int a_dk = (lane >> 4) << 3;
    const int quad = lane >> 3;
    const int b_dc = (lane & 7) + ((quad & 2) ? 8 : 0);
    const int b_dk = (quad & 1) << 3;

    const __nv_bfloat16* Ag = Ain + (size_t)m0 * 1024;

    auto fillC = [&](int c) {
        int ny2 = c >> 5, kt2 = c & 31, st = c & 3;
        __nv_bfloat16* As = (__nv_bfloat16*)(smem + st*10240);
        __nv_bfloat16* Bs = (__nv_bfloat16*)(smem + 40960 + st*10240);
        const __nv_bfloat16* Wg = Wt + (size_t)(ny2*128) * 1024 + kt2*32;
        const __nv_bfloat16* Ac = Ag + kt2*32;
#pragma unroll
        for (int i = 0; i < 2; i++) {
            int idx = tid + 256*i;
            int row = idx >> 2, seg = idx & 3;
            cp_async16(As + row*B_STR + seg*8, Ac + (size_t)row*1024 + seg*8);
            cp_async16(Bs + row*B_STR + seg*8, Wg + (size_t)row*1024 + seg*8);
        }
        cp_commit();
    };
    fillC(0); fillC(1); fillC(2);

    int ci = 0;
    for (int ny = 0; ny < NY; ny++) {
        float acc[2][8][4];
#pragma unroll
        for (int i = 0; i < 2; i++)
#pragma unroll
            for (int j = 0; j < 8; j++)
#pragma unroll
                for (int q = 0; q < 4; q++) acc[i][j][q] = 0.f;

        for (int kt = 0; kt < KT; kt++, ci++) {
            cp_wait2();
            __syncthreads();
            int st = ci & 3;
            const u32 asb = sbase + (u32)st*10240;
            const u32 bsb = sbase + 40960u + (u32)st*10240;
#pragma unroll
            for (int ks = 0; ks < 2; ks++) {
                u32 af[2][4], bf[8][2];
#pragma unroll
                for (int mt = 0; mt < 2; mt++) {
                    u32 aaddr = asb + (u32)(((arow + mt*16 + a_dr)*B_STR + ks*16 + a_dk) * 2);
                    ldsm4(af[mt][0], af[mt][1], af[mt][2], af[mt][3], aaddr);
                }
#pragma unroll
                for (int p = 0; p < 4; p++) {
                    u32 baddr = bsb + (u32)(((bcol + p*16 + b_dc)*B_STR + ks*16 + b_dk) * 2);
                    ldsm4(bf[2*p][0], bf[2*p][1], bf[2*p+1][0], bf[2*p+1][1], baddr);
                }
#pragma unroll
                for (int mt = 0; mt < 2; mt++)
#pragma unroll
                    for (int nt = 0; nt < 8; nt++)
                        mma_bf16(acc[mt][nt], af[mt], bf[nt]);
            }
            if (ci + 3 < TOT) fillC(ci + 3);
            else cp_commit();
        }

        const int ncol0 = ny * 128;
#pragma unroll
        for (int nt = 0; nt < 8; nt++) {
            int colG = ncol0 + bcol + nt*8 + 2*tig;
            float b0 = bias[colG], b1 = bias[colG + 1];
            float g0 = gate[b*256 + colG], g1 = gate[b*256 + colG + 1];
#pragma unroll
            for (int mt = 0; mt < 2; mt++) {
                size_t r0 = (size_t)m0 + arow + mt*16 + g;
                size_t r1 = r0 + 8;
                float2 q0 = *(const float2*)(R + r0*256 + colG);
                float2 q1 = *(const float2*)(R + r1*256 + colG);
                float v00 = acc[mt][nt][0] + b0 + q0.x*g0, v01 = acc[mt][nt][1] + b1 + q0.y*g1;
                float v10 = acc[mt][nt][2] + b0 + q1.x*g0, v11 = acc[mt][nt][3] + b1 + q1.y*g1;
                *(float2*)(Cout + r0*256 + colG) = make_float2(v00, v01);
                *(float2*)(Cout + r1*256 + colG) = make_float2(v10, v11);
            }
        }
    }
}

// ============================================================================
// Tensor-core window attention: one warp per (window, head).
// Q fragments hoisted out of the key-chunk loop (ck-invariant).
// ============================================================================
__global__ void __launch_bounds__(128) k_attn_tc(const __nv_bfloat16* __restrict__ qkv,
                                                 const float* __restrict__ rel_bias,
                                                 __nv_bfloat16* __restrict__ o) {
    __shared__ __align__(16) __nv_bfloat16 VtAll[4][32][72];
    __shared__ float sbAll[4][226];

    const int lane = threadIdx.x & 31;
    const int wid  = threadIdx.x >> 5;
    const int g = lane >> 2, tig = lane & 3;
    const int win = blockIdx.x;
    const int h = blockIdx.y * 4 + wid;

    __nv_bfloat16 (*Vt)[72] = VtAll[wid];
    float* sb = sbAll[wid];
    const u32 vtb = (u32)__cvta_generic_to_shared(&VtAll[wid][0][0]);

    const int quad = lane >> 3;
    const int v_dc = (lane & 7) + ((quad & 2) ? 8 : 0);
    const int v_dk = (quad & 1) << 3;

    const __nv_bfloat16* qw = qkv + (size_t)win * 64 * 768 + h * 32;
    const __nv_bfloat16* kw = qw + 256;
    const __nv_bfloat16* vw = qw + 512;

    for (int r = lane; r < 225; r += 32) sb[r] = rel_bias[r*NH + h];

#pragma unroll
    for (int i = 0; i < 32; i++) {
        int idx = lane + 32*i;
        int n = idx >> 4, dp = idx & 15;
        u32 u = *(const u32*)(vw + (size_t)n*768 + 2*dp);
        __nv_bfloat162 v2 = *(__nv_bfloat162*)&u;
        Vt[2*dp  ][n] = v2.x;
        Vt[2*dp+1][n] = v2.y;
    }
    __syncwarp();

    // hoisted Q fragments: aQ[ks][mt][4]
    u32 aQ[2][4][4];
#pragma unroll
    for (int ks = 0; ks < 2; ks++) {
        const int kc = 16*ks + 2*tig;
#pragma unroll
        for (int mt = 0; mt < 4; mt++) {
            const __nv_bfloat16* q0 = qw + (size_t)(mt*16 + g)*768 + kc;
            aQ[ks][mt][0] = *(const u32*)(q0);
            aQ[ks][mt][1] = *(const u32*)(q0 + 8*768);
            aQ[ks][mt][2] = *(const u32*)(q0 + 8);
            aQ[ks][mt][3] = *(const u32*)(q0 + 8*768 + 8);
        }
    }

    float O[4][4][4];
#pragma unroll
    for (int a = 0; a < 4; a++)
#pragma unroll
        for (int bq = 0; bq < 4; bq++)
#pragma unroll
            for (int c = 0; c < 4; c++) O[a][bq][c] = 0.f;
    float mrow[8], lrow[8];
#pragma unroll
    for (int r = 0; r < 8; r++) { mrow[r] = -1e30f; lrow[r] = 0.f; }

#pragma unroll 1
    for (int ck = 0; ck < 2; ck++) {
        float S[4][4][4];
#pragma unroll
        for (int a = 0; a < 4; a++)
#pragma unroll
            for (int bq = 0; bq < 4; bq++)
#pragma unroll
                for (int c = 0; c < 4; c++) S[a][bq][c] = 0.f;

#pragma unroll
        for (int ks = 0; ks < 2; ks++) {
            const int kc = 16*ks + 2*tig;
            u32 bK[4][2];
#pragma unroll
            for (int nt = 0; nt < 4; nt++) {
                const __nv_bfloat16* k0 = kw + (size_t)(ck*32 + nt*8 + g)*768 + kc;
                bK[nt][0] = *(const u32*)(k0);
                bK[nt][1] = *(const u32*)(k0 + 8);
            }
#pragma unroll
            for (int mt = 0; mt < 4; mt++)
#pragma unroll
                for (int nt = 0; nt < 4; nt++)
                    mma_bf16(S[mt][nt], aQ[ks][mt], bK[nt]);
        }

#pragma unroll
        for (int mt = 0; mt < 4; mt++)
#pragma unroll
            for (int nt = 0; nt < 4; nt++)
#pragma unroll
                for (int rr = 0; rr < 2; rr++)
#pragma unroll
                    for (int e = 0; e < 2; e++) {
                        int di = 2*mt + rr - (4*ck + nt) + 7;
                        int dj = g - (2*tig + e) + 7;
                        S[mt][nt][rr*2+e] = S[mt][nt][rr*2+e] * 0.17677669529663687f
                                          + sb[di*15 + dj];
                    }

#pragma unroll
        for (int mt = 0; mt < 4; mt++)
#pragma unroll
            for (int rr = 0; rr < 2; rr++) {
                const int r8 = mt*2 + rr;
                float mloc = -1e30f;
#pragma unroll
                for (int nt = 0; nt < 4; nt++) {
                    mloc = fmaxf(mloc, S[mt][nt][rr*2]);
                    mloc = fmaxf(mloc, S[mt][nt][rr*2+1]);
                }
                mloc = fmaxf(mloc, __shfl_xor_sync(0xffffffffu, mloc, 1));
                mloc = fmaxf(mloc, __shfl_xor_sync(0xffffffffu, mloc, 2));
                float newm = fmaxf(mrow[r8], mloc);
                float fsc = __expf(mrow[r8] - newm);
                mrow[r8] = newm;
                float rsum = 0.f;
#pragma unroll
                for (int nt = 0; nt < 4; nt++) {
                    float p0 = __expf(S[mt][nt][rr*2]   - newm);
                    float p1 = __expf(S[mt][nt][rr*2+1] - newm);
                    S[mt][nt][rr*2] = p0; S[mt][nt][rr*2+1] = p1;
                    rsum += p0 + p1;
                }
                rsum += __shfl_xor_sync(0xffffffffu, rsum, 1);
                rsum += __shfl_xor_sync(0xffffffffu, rsum, 2);
                lrow[r8] = lrow[r8]*fsc + rsum;
#pragma unroll
                for (int nt2 = 0; nt2 < 4; nt2++) {
                    O[mt][nt2][rr*2]   *= fsc;
                    O[mt][nt2][rr*2+1] *= fsc;
                }
            }

#pragma unroll
        for (int ks2 = 0; ks2 < 2; ks2++) {
            u32 bV[4][2];
#pragma unroll
            for (int p = 0; p < 2; p++) {
                u32 vaddr = vtb + (u32)(((p*16 + v_dc)*72 + ck*32 + ks2*16 + v_dk) * 2);
                ldsm4(bV[2*p][0], bV[2*p][1], bV[2*p+1][0], bV[2*p+1][1], vaddr);
            }
#pragma unroll
            for (int mt = 0; mt < 4; mt++) {
                u32 pa[4];
                pa[0] = packbf(S[mt][2*ks2  ][0], S[mt][2*ks2  ][1]);
                pa[1] = packbf(S[mt][2*ks2  ][2], S[mt][2*ks2  ][3]);
                pa[2] = packbf(S[mt][2*ks2+1][0], S[mt][2*ks2+1][1]);
                pa[3] = packbf(S[mt][2*ks2+1][2], S[mt][2*ks2+1][3]);
#pragma unroll
                for (int nt2 = 0; nt2 < 4; nt2++)
                    mma_bf16(O[mt][nt2], pa, bV[nt2]);
            }
        }
    }

    float invl[8];
#pragma unroll
    for (int r = 0; r < 8; r++) invl[r] = 1.f / lrow[r];
    __nv_bfloat16* ob = o + (size_t)win * 64 * 256 + h * 32;
#pragma unroll
    for (int mt = 0; mt < 4; mt++)
#pragma unroll
        for (int nt2 = 0; nt2 < 4; nt2++) {
            __nv_bfloat16* p0 = ob + (size_t)(mt*16 + g)*256 + nt2*8 + 2*tig;
            *(u32*)(p0)         = packbf(O[mt][nt2][0]*invl[2*mt],   O[mt][nt2][1]*invl[2*mt]);
            *(u32*)(p0 + 8*256) = packbf(O[mt][nt2][2]*invl[2*mt+1], O[mt][nt2][3]*invl[2*mt+1]);
        }
}

// -------------------- SE gate from completed pooled sums --------------------
__global__ void __launch_bounds__(256) k_pool_gate(const float* __restrict__ part,
                                                   const float* __restrict__ w1,
                                                   const float* __restrict__ b1,
                                                   const float* __restrict__ w2,
                                                   const float* __restrict__ b2,
                                                   float* __restrict__ gate) {
    int b = blockIdx.x;
    float pooled = part[b*256 + threadIdx.x] * (1.f / (float)TOK_PER_B);
    __shared__ float sp[256];
    __shared__ float hid[16];
    sp[threadIdx.x] = pooled;
    __syncthreads();
    if (threadIdx.x < 16) {
        float a = b1[threadIdx.x];
        for (int c = 0; c < 256; c++) a = fmaf(sp[c], w1[c*16 + threadIdx.x], a);
        hid[threadIdx.x] = fmaxf(a, 0.f);
    }
    __syncthreads();
    float g = b2[threadIdx.x];
#pragma unroll
    for (int j = 0; j < 16; j++) g = fmaf(hid[j], w2[j*256 + threadIdx.x], g);
    gate[b*256 + threadIdx.x] = 1.f / (1.f + __expf(-g));
}

// ---------------------------------------------------------------------------
extern "C" void kernel_launch(void* const* d_in, const int* in_sizes, int n_in,
                              void* d_out, int out_size) {
    const float* x      = (const float*)d_in[0];
    const float* n1_g   = (const float*)d_in[1];
    const float* n1_b   = (const float*)d_in[2];
    const float* qkv_w  = (const float*)d_in[3];
    const float* qkv_b  = (const float*)d_in[4];
    const float* proj_w = (const float*)d_in[5];
    const float* proj_b = (const float*)d_in[6];
    const float* rel_b  = (const float*)d_in[7];
    const float* se_w1  = (const float*)d_in[8];
    const float* se_b1  = (const float*)d_in[9];
    const float* se_w2  = (const float*)d_in[10];
    const float* se_b2  = (const float*)d_in[11];
    const float* n3_g   = (const float*)d_in[12];
    const float* n3_b   = (const float*)d_in[13];
    const float* mlp_w1 = (const float*)d_in[14];
    const float* mlp_b1 = (const float*)d_in[15];
    const float* mlp_w2 = (const float*)d_in[16];
    const float* mlp_b2 = (const float*)d_in[17];
    float* out = (float*)d_out;

    float *wins, *hbuf, *big, *part, *gate, *wb;
    cudaGetSymbolAddress((void**)&wins, g_wins);
    cudaGetSymbolAddress((void**)&hbuf, g_h);
    cudaGetSymbolAddress((void**)&big,  g_big);
    cudaGetSymbolAddress((void**)&part, g_part);
    cudaGetSymbolAddress((void**)&gate, g_gate);
    cudaGetSymbolAddress((void**)&wb,   g_wb);

    __nv_bfloat16* wbf   = (__nv_bfloat16*)wb;
    __nv_bfloat16* qkvW  = wbf;            // [768,256]
    __nv_bfloat16* projW = wbf + 196608;   // [256,256]
    __nv_bfloat16* w1W   = wbf + 262144;   // [1024,256]
    __nv_bfloat16* w2W   = wbf + 524288;   // [256,1024]
    __nv_bfloat16* bigb  = (__nv_bfloat16*)big;
    __nv_bfloat16* hb    = (__nv_bfloat16*)hbuf;

    cudaFuncSetAttribute(k_gemm_smA, cudaFuncAttributeMaxDynamicSharedMemorySize, SMA_SMEM);
    cudaFuncSetAttribute(k_gemm_sA,  cudaFuncAttributeMaxDynamicSharedMemorySize, SA_SMEM);

    dim3 b328(32, 8);
    dim3 gtr(WW_/32, HH, BATCH*8);

    // launch order chosen so ncu (-s 5 -c 1) captures the QKV GEMM (6th kernel)
    cudaMemsetAsync(part, 0, 1024 * sizeof(float));
    k_winpart<<<gtr, b328>>>(x, wins);                            // 1
    k_wprep<<<dim3(24, 8),  b328>>>(qkv_w,  qkvW,  256, 768);     // 2
    k_wprep<<<dim3(8,  8),  b328>>>(proj_w, projW, 256, 256);     // 3
    k_wprep<<<dim3(32, 8),  b328>>>(mlp_w1, w1W,   256, 1024);    // 4
    k_wprep<<<dim3(8,  32), b328>>>(mlp_w2, w2W,   1024, 256);    // 5
    k_gemm_smA<<<NTOK/128, 256, SMA_SMEM>>>(wins, 0, n1_g, n1_b, nullptr,   // 6 <- profiled
                                            qkvW, qkv_b, nullptr,
                                            bigb, 1, 0, 768, nullptr);
    k_attn_tc<<<dim3(NWIN, 2), 128>>>(bigb, rel_b, hb);
    k_gemm_smA<<<NTOK/128, 256, SMA_SMEM>>>(hb, 1, nullptr, nullptr, nullptr,
                                            projW, proj_b, wins,
                                            wins, 0, 0, 256, part);
    k_pool_gate<<<BATCH, 256>>>(part, se_w1, se_b1, se_w2, se_b2, gate);
    k_gemm_smA<<<NTOK/128, 256, SMA_SMEM>>>(wins, 0, n3_g, n3_b, gate,
                                            w1W, mlp_b1, nullptr,
                                            bigb, 1, 1, 1024, nullptr);
    k_gemm_sA<<<NTOK/128, 256, SA_SMEM>>>(bigb, w2W, mlp_b2, wins, gate, hbuf);
    k_winrev<<<gtr, b328>>>(hbuf, out);
}